// round 12
// baseline (speedup 1.0000x reference)
#include <cuda_runtime.h>
#include <cuda_fp16.h>
#include <math_constants.h>
#include <stdint.h>

#define BATCH 4
#define SEQ   2048
#define DM    1024
#define MROWS (BATCH * SEQ)

#define LO_SCALE  2048.0f
#define INV_LO    (1.0f / 2048.0f)

// ---- shared tiling constants -------------------------------------------------
#define TM 128
#define TN 128
#define TILE_BYTES (128 * 128)        // 16 KB per operand tile (128 rows x 128B)
#define STAGE_BYTES (4 * TILE_BYTES)  // 4 tiles = 64 KB
#define SMEM_DYN (3 * STAGE_BYTES)    // 192 KB, 3-stage
#define BK_F16 64                     // f16 elems per chunk (128B row)
#define BK_I8  128                    // s8  elems per chunk (128B row)

typedef __half h16;

// ---- scratch (static __device__: allocation-free) -------------------------------
#define AL1K __align__(1024)
// int8 limbs
__device__ AL1K int8_t g_x1 [MROWS * DM];
__device__ AL1K int8_t g_x2 [MROWS * DM];
__device__ AL1K int8_t g_wa1[2 * DM * DM];   // [Wk ; Wo^T]
__device__ AL1K int8_t g_wa2[2 * DM * DM];
__device__ AL1K int8_t g_wb1[2 * DM * DM];   // [Wq ; Wv]
__device__ AL1K int8_t g_wb2[2 * DM * DM];
__device__ AL1K int8_t g_g1 [2 * DM * DM];   // [GT ; HT]
__device__ AL1K int8_t g_g2 [2 * DM * DM];
__device__ AL1K int8_t g_qg1[MROWS * DM];    // QG
__device__ AL1K int8_t g_qg2[MROWS * DM];
// f16 limbs
__device__ AL1K h16   g_gh [2 * DM * DM];    // GT/HT f16 (pre-quant)
__device__ AL1K h16   g_gl [2 * DM * DM];
__device__ AL1K h16   g_qxh[(size_t)2 * MROWS * DM];  // [QG ; XH]
__device__ AL1K h16   g_qxl[(size_t)2 * MROWS * DM];
__device__ AL1K h16   g_xth[MROWS * DM];     // XH^T per batch [B][D][S]
__device__ AL1K h16   g_ph [(size_t)BATCH * SEQ * SEQ];
__device__ AL1K h16   g_pl [(size_t)BATCH * SEQ * SEQ];
// fp32
__device__ AL1K float g_p  [(size_t)BATCH * SEQ * SEQ];
__device__ AL1K float g_w2 [DM];
__device__ AL1K float g_v  [MROWS];
__device__ AL1K float g_rb [DM];
// quantization scales (abs-max bits); slots: 0:x 1:Wk 2:WoT 3:Wq 4:Wv 5:GT 6:HT 7:QG
__device__ uint32_t g_maxbits[8];

__device__ __forceinline__ float dscale(int s) {
    return __uint_as_float(g_maxbits[s]) * (1.0f / 127.0f);
}

// ---- PTX helpers -----------------------------------------------------------------
__device__ __forceinline__ uint32_t s2u(const void* p) {
    uint32_t a;
    asm("{ .reg .u64 t; cvta.to.shared.u64 t, %1; cvt.u32.u64 %0, t; }" : "=r"(a) : "l"(p));
    return a;
}
__device__ __forceinline__ void cp16(uint32_t saddr, const void* gaddr) {
    asm volatile("cp.async.cg.shared.global [%0], [%1], 16;" :: "r"(saddr), "l"(gaddr));
}
__device__ __forceinline__ void cp_commit() { asm volatile("cp.async.commit_group;"); }
__device__ __forceinline__ void cp_wait2()  { asm volatile("cp.async.wait_group 2;" ::: "memory"); }

__device__ __forceinline__ void ldm4(uint32_t* r, uint32_t addr) {
    asm volatile("ldmatrix.sync.aligned.m8n8.x4.shared.b16 {%0,%1,%2,%3}, [%4];"
                 : "=r"(r[0]), "=r"(r[1]), "=r"(r[2]), "=r"(r[3]) : "r"(addr));
}
__device__ __forceinline__ void mma_f32(float* c, const uint32_t* a, const uint32_t* b) {
    asm volatile(
        "mma.sync.aligned.m16n8k16.row.col.f32.f16.f16.f32 "
        "{%0,%1,%2,%3}, {%4,%5,%6,%7}, {%8,%9}, {%0,%1,%2,%3};"
        : "+f"(c[0]), "+f"(c[1]), "+f"(c[2]), "+f"(c[3])
        : "r"(a[0]), "r"(a[1]), "r"(a[2]), "r"(a[3]), "r"(b[0]), "r"(b[1]));
}
__device__ __forceinline__ void mma_f16(uint32_t* c, const uint32_t* a, const uint32_t* b) {
    asm volatile(
        "mma.sync.aligned.m16n8k16.row.col.f16.f16.f16.f16 "
        "{%0,%1}, {%2,%3,%4,%5}, {%6,%7}, {%0,%1};"
        : "+r"(c[0]), "+r"(c[1])
        : "r"(a[0]), "r"(a[1]), "r"(a[2]), "r"(a[3]), "r"(b[0]), "r"(b[1]));
}
__device__ __forceinline__ void mma_s32(int* c, const uint32_t* a, const uint32_t* b) {
    asm volatile(
        "mma.sync.aligned.m16n8k32.row.col.s32.s8.s8.s32 "
        "{%0,%1,%2,%3}, {%4,%5,%6,%7}, {%8,%9}, {%0,%1,%2,%3};"
        : "+r"(c[0]), "+r"(c[1]), "+r"(c[2]), "+r"(c[3])
        : "r"(a[0]), "r"(a[1]), "r"(a[2]), "r"(a[3]), "r"(b[0]), "r"(b[1]));
}
__device__ __forceinline__ uint32_t pk2(float a, float b) {
    __half2 t = __floats2half2_rn(a, b);
    return *reinterpret_cast<uint32_t*>(&t);
}
__device__ __forceinline__ int8_t clamp_q1(float q) {
    return (int8_t)max(-127, min(127, __float2int_rn(q)));
}

// ============================================================================
// INT8 GEMM: C[M,N] = scale*sA*sB*((A1+A2/128)[M,K] @ ((B1+B2/128)[N,K])^T)
//   3 IMMA terms: acc1 = A1B1; acc2 = A1B2 + A2B1 (exact s32).
//   OUTMODE 0: fp32 out (Cf).  OUTMODE 1: f16 limb out (Ch, Cl; lo x2048).
//   CAUSAL: skip 128x128 tiles strictly above diagonal.
//   Scales read from g_maxbits[idxA + z*strA], [idxB + z*strB].
// ============================================================================
template<int OUTMODE, bool CAUSAL>
__global__ __launch_bounds__(256, 1)
void tc_gemm_i8(const int8_t* __restrict__ A1, const int8_t* __restrict__ A2,
                const int8_t* __restrict__ B1, const int8_t* __restrict__ B2,
                float* __restrict__ Cf, h16* __restrict__ Ch, h16* __restrict__ Cl,
                int Kfull, int ldA, int ldB, int ldC, float scale,
                size_t sA, size_t sB, size_t sC,
                int idxA, int strA, int idxB, int strB)
{
    const int m0 = blockIdx.y * TM;
    const int n0 = blockIdx.x * TN;
    if (CAUSAL && n0 > m0) return;

    const int z = blockIdx.z;
    A1 += (size_t)z * sA;  A2 += (size_t)z * sA;
    B1 += (size_t)z * sB;  B2 += (size_t)z * sB;

    extern __shared__ char dsm[];
    const uint32_t smem = s2u(dsm);

    const int tid  = threadIdx.x;
    const int wid  = tid >> 5;
    const int lane = tid & 31;
    const int wm   = wid & 3;    // 4 warp-rows  (32 M each)
    const int wn   = wid >> 2;   // 2 warp-cols  (64 N each)

    const int nchunk = Kfull / BK_I8;

    // ---- loader: each thread = half a row (4x16B segs) of each of 4 tiles ----
    const int lrow = tid >> 1;
    const int sb   = (tid & 1) * 4;
    const char* gp[4];
    uint32_t    so[4][4];
    {
        const int8_t* bases[4] = {A1, A2, B1, B2};
        #pragma unroll
        for (int t = 0; t < 4; t++) {
            const int off = (t < 2) ? m0 : n0;
            const int ld  = (t < 2) ? ldA : ldB;
            gp[t] = (const char*)(bases[t] + (size_t)(off + lrow) * ld);
            #pragma unroll
            for (int j = 0; j < 4; j++) {
                const int seg = sb + j;
                so[t][j] = (uint32_t)(t * TILE_BYTES + lrow * 128 +
                                      ((seg ^ (lrow & 7)) << 4));
            }
        }
    }

    auto load_stage = [&](int slot, int chunk) {
        if (chunk < nchunk) {
            const uint32_t s0 = smem + slot * STAGE_BYTES;
            const size_t goff = (size_t)chunk * 128;   // 128 s8 = 128 bytes
            #pragma unroll
            for (int t = 0; t < 4; t++) {
                #pragma unroll
                for (int j = 0; j < 4; j++)
                    cp16(s0 + so[t][j], gp[t] + goff + (size_t)(sb + j) * 16);
            }
        }
        cp_commit();
    };

    int acc1[2][8][4];
    int acc2[2][8][4];
    #pragma unroll
    for (int a = 0; a < 2; a++)
        #pragma unroll
        for (int b = 0; b < 8; b++)
            #pragma unroll
            for (int c = 0; c < 4; c++) { acc1[a][b][c] = 0; acc2[a][b][c] = 0; }

    load_stage(0, 0);
    load_stage(1, 1);
    load_stage(2, 2);

    const int a_r  = lane & 15;
    const int a_kh = lane >> 4;
    const int b_nl = ((lane >> 4) & 1) * 8 + (lane & 7);
    const int b_kh = (lane >> 3) & 1;

    for (int i = 0; i < nchunk; i++) {
        cp_wait2();
        __syncthreads();
        const uint32_t s0 = smem + (i % 3) * STAGE_BYTES;

        #pragma unroll
        for (int kk = 0; kk < 4; kk++) {       // each kk = K32 (32 bytes)
            uint32_t a1f[2][4], a2f[2][4], b1f[4][4], b2f[4][4];
            #pragma unroll
            for (int mt = 0; mt < 2; mt++) {
                const int row = wm * 32 + mt * 16 + a_r;
                const int seg = kk * 2 + a_kh;
                const uint32_t off = (uint32_t)(row * 128 + ((seg ^ (row & 7)) << 4));
                ldm4(a1f[mt], s0 + 0 * TILE_BYTES + off);
                ldm4(a2f[mt], s0 + 1 * TILE_BYTES + off);
            }
            #pragma unroll
            for (int p = 0; p < 4; p++) {
                const int row = wn * 64 + p * 16 + b_nl;
                const int seg = kk * 2 + b_kh;
                const uint32_t off = (uint32_t)(row * 128 + ((seg ^ (row & 7)) << 4));
                ldm4(b1f[p], s0 + 2 * TILE_BYTES + off);
                ldm4(b2f[p], s0 + 3 * TILE_BYTES + off);
            }
            #pragma unroll
            for (int mt = 0; mt < 2; mt++)
                #pragma unroll
                for (int nt = 0; nt < 8; nt++)
                    mma_s32(acc1[mt][nt], a1f[mt], &b1f[nt >> 1][(nt & 1) * 2]);
            #pragma unroll
            for (int mt = 0; mt < 2; mt++)
                #pragma unroll
                for (int nt = 0; nt < 8; nt++)
                    mma_s32(acc2[mt][nt], a1f[mt], &b2f[nt >> 1][(nt & 1) * 2]);
            #pragma unroll
            for (int mt = 0; mt < 2; mt++)
                #pragma unroll
                for (int nt = 0; nt < 8; nt++)
                    mma_s32(acc2[mt][nt], a2f[mt], &b1f[nt >> 1][(nt & 1) * 2]);
        }
        __syncthreads();
        load_stage(i % 3, i + 3);
    }

    const float fs = dscale(idxA + z * strA) * dscale(idxB + z * strB) * scale;

    #pragma unroll
    for (int mt = 0; mt < 2; mt++) {
        #pragma unroll
        for (int h = 0; h < 2; h++) {
            const int row = m0 + wm * 32 + mt * 16 + (lane >> 2) + 8 * h;
            #pragma unroll
            for (int nt = 0; nt < 8; nt++) {
                const int col = n0 + wn * 64 + nt * 8 + (lane & 3) * 2;
                float v0 = ((float)acc1[mt][nt][2 * h + 0] +
                            (float)acc2[mt][nt][2 * h + 0] * 0.0078125f) * fs;
                float v1 = ((float)acc1[mt][nt][2 * h + 1] +
                            (float)acc2[mt][nt][2 * h + 1] * 0.0078125f) * fs;
                if (OUTMODE == 0) {
                    *reinterpret_cast<float2*>(
                        Cf + (size_t)z * sC + (size_t)row * ldC + col) =
                        make_float2(v0, v1);
                } else {
                    float h0 = __half2float(__float2half_rn(v0));
                    float h1 = __half2float(__float2half_rn(v1));
                    *reinterpret_cast<uint32_t*>(
                        Ch + (size_t)z * sC + (size_t)row * ldC + col) = pk2(h0, h1);
                    *reinterpret_cast<uint32_t*>(
                        Cl + (size_t)z * sC + (size_t)row * ldC + col) =
                        pk2((v0 - h0) * LO_SCALE, (v1 - h1) * LO_SCALE);
                }
            }
        }
    }
}

// ============================================================================
// F16 GEMM for P@V only (proven config; 2-term: P full 22-bit, XH hi 11-bit)
// ============================================================================
__global__ __launch_bounds__(256, 1)
void tc_gemm_pv(const h16* __restrict__ Ah, const h16* __restrict__ Al,
                const h16* __restrict__ Bh,
                const float* __restrict__ bias, float* __restrict__ Cf,
                int ldA, int ldB, int ldC,
                size_t sA, size_t sB, size_t sC)
{
    const int bmi = gridDim.y - 1 - blockIdx.y;     // heavy CTAs first
    const int m0 = bmi * TM;
    const int n0 = blockIdx.x * TN;
    const int z = blockIdx.z;
    Ah += (size_t)z * sA;  Al += (size_t)z * sA;
    Bh += (size_t)z * sB;

    extern __shared__ char dsm[];
    const uint32_t smem = s2u(dsm);

    const int tid  = threadIdx.x;
    const int wid  = tid >> 5;
    const int lane = tid & 31;
    const int wm   = wid & 3;
    const int wn   = wid >> 2;

    const int nchunk = (m0 + TM) / BK_F16;          // causal K truncation

    const int lrow = tid >> 1;
    const int sb   = (tid & 1) * 4;
    const char* gp[3];
    uint32_t    so[3][4];
    {
        const h16* bases[3] = {Ah, Al, Bh};
        #pragma unroll
        for (int t = 0; t < 3; t++) {
            const int off = (t < 2) ? m0 : n0;
            const int ld  = (t < 2) ? ldA : ldB;
            gp[t] = (const char*)(bases[t] + (size_t)(off + lrow) * ld);
            #pragma unroll
            for (int j = 0; j < 4; j++) {
                const int seg = sb + j;
                so[t][j] = (uint32_t)(t * TILE_BYTES + lrow * 128 +
                                      ((seg ^ (lrow & 7)) << 4));
            }
        }
    }

    auto load_stage = [&](int slot, int chunk) {
        if (chunk < nchunk) {
            const uint32_t s0 = smem + slot * STAGE_BYTES;
            const size_t goff = (size_t)chunk * 128;
            #pragma unroll
            for (int t = 0; t < 3; t++) {
                #pragma unroll
                for (int j = 0; j < 4; j++)
                    cp16(s0 + so[t][j], gp[t] + goff + (size_t)(sb + j) * 16);
            }
        }
        cp_commit();
    };

    float    accf[2][8][4];
    uint32_t acch[2][8][2];
    #pragma unroll
    for (int a = 0; a < 2; a++)
        #pragma unroll
        for (int b = 0; b < 8; b++) {
            #pragma unroll
            for (int c = 0; c < 4; c++) accf[a][b][c] = 0.f;
            acch[a][b][0] = 0u; acch[a][b][1] = 0u;
        }

    load_stage(0, 0);
    load_stage(1, 1);
    load_stage(2, 2);

    const int a_r  = lane & 15;
    const int a_kh = lane >> 4;
    const int b_nl = ((lane >> 4) & 1) * 8 + (lane & 7);
    const int b_kh = (lane >> 3) & 1;

    for (int i = 0; i < nchunk; i++) {
        cp_wait2();
        __syncthreads();
        const uint32_t s0 = smem + (i % 3) * STAGE_BYTES;

        #pragma unroll
        for (int kk = 0; kk < 4; kk++) {
            uint32_t ahf[2][4], alf[2][4], bhf[4][4];
            #pragma unroll
            for (int mt = 0; mt < 2; mt++) {
                const int row = wm * 32 + mt * 16 + a_r;
                const int seg = kk * 2 + a_kh;
                const uint32_t off = (uint32_t)(row * 128 + ((seg ^ (row & 7)) << 4));
                ldm4(ahf[mt], s0 + 0 * TILE_BYTES + off);
                ldm4(alf[mt], s0 + 1 * TILE_BYTES + off);
            }
            #pragma unroll
            for (int p = 0; p < 4; p++) {
                const int row = wn * 64 + p * 16 + b_nl;
                const int seg = kk * 2 + b_kh;
                const uint32_t off = (uint32_t)(row * 128 + ((seg ^ (row & 7)) << 4));
                ldm4(bhf[p], s0 + 2 * TILE_BYTES + off);
            }
            #pragma unroll
            for (int mt = 0; mt < 2; mt++)
                #pragma unroll
                for (int nt = 0; nt < 8; nt++)
                    mma_f32(accf[mt][nt], ahf[mt], &bhf[nt >> 1][(nt & 1) * 2]);
            #pragma unroll
            for (int mt = 0; mt < 2; mt++)
                #pragma unroll
                for (int nt = 0; nt < 8; nt++)
                    mma_f16(acch[mt][nt], alf[mt], &bhf[nt >> 1][(nt & 1) * 2]);
        }
        __syncthreads();
        load_stage(i % 3, i + 3);
    }

    #pragma unroll
    for (int mt = 0; mt < 2; mt++) {
        #pragma unroll
        for (int h = 0; h < 2; h++) {
            const int row = m0 + wm * 32 + mt * 16 + (lane >> 2) + 8 * h;
            #pragma unroll
            for (int nt = 0; nt < 8; nt++) {
                const int col = n0 + wn * 64 + nt * 8 + (lane & 3) * 2;
                const __half2 hc = *reinterpret_cast<const __half2*>(&acch[mt][nt][h]);
                float v0 = accf[mt][nt][2 * h + 0] + __low2float(hc)  * INV_LO;
                float v1 = accf[mt][nt][2 * h + 1] + __high2float(hc) * INV_LO;
                const float2 bb = *reinterpret_cast<const float2*>(bias + col);
                v0 += bb.x; v1 += bb.y;
                *reinterpret_cast<float2*>(
                    Cf + (size_t)z * sC + (size_t)row * ldC + col) =
                    make_float2(v0, v1);
            }
        }
    }
}

// ============================================================================
// quantization + prep kernels
// ============================================================================
__global__ void maxabs_f32(const float* __restrict__ in, int n, int slot)
{
    __shared__ float red[256];
    float m = 0.f;
    for (int i = blockIdx.x * 256 + threadIdx.x; i < n; i += gridDim.x * 256)
        m = fmaxf(m, fabsf(in[i]));
    red[threadIdx.x] = m; __syncthreads();
    for (int s = 128; s > 0; s >>= 1) {
        if (threadIdx.x < s) red[threadIdx.x] = fmaxf(red[threadIdx.x], red[threadIdx.x + s]);
        __syncthreads();
    }
    if (threadIdx.x == 0) atomicMax(&g_maxbits[slot], __float_as_uint(red[0]));
}

__global__ void maxabs_h2(const h16* __restrict__ hh, const h16* __restrict__ hl,
                          size_t off, int n, int slot)
{
    __shared__ float red[256];
    float m = 0.f;
    for (int i = blockIdx.x * 256 + threadIdx.x; i < n; i += gridDim.x * 256) {
        float v = __half2float(hh[off + i]) + __half2float(hl[off + i]) * INV_LO;
        m = fmaxf(m, fabsf(v));
    }
    red[threadIdx.x] = m; __syncthreads();
    for (int s = 128; s > 0; s >>= 1) {
        if (threadIdx.x < s) red[threadIdx.x] = fmaxf(red[threadIdx.x], red[threadIdx.x + s]);
        __syncthreads();
    }
    if (threadIdx.x == 0) atomicMax(&g_maxbits[slot], __float_as_uint(red[0]));
}

__global__ void quant_f32(const float* __restrict__ in,
                          int8_t* __restrict__ q1, int8_t* __restrict__ q2,
                          int n, int slot)
{
    int i = blockIdx.x * blockDim.x + threadIdx.x;
    if (i >= n) return;
    const float inv = 1.0f / dscale(slot);
    float a = in[i] * inv;
    int8_t c1 = clamp_q1(a);
    q1[i] = c1;
    q2[i] = (int8_t)__float2int_rn((a - (float)c1) * 128.0f);
}

__global__ void quant_h2(const h16* __restrict__ hh, const h16* __restrict__ hl,
                         size_t off, int8_t* __restrict__ q1, int8_t* __restrict__ q2,
                         int n, int slot)
{
    int i = blockIdx.x * blockDim.x + threadIdx.x;
    if (i >= n) return;
    const float inv = 1.0f / dscale(slot);
    float v = __half2float(hh[off + i]) + __half2float(hl[off + i]) * INV_LO;
    float a = v * inv;
    int8_t c1 = clamp_q1(a);
    q1[i] = c1;
    q2[i] = (int8_t)__float2int_rn((a - (float)c1) * 128.0f);
}

// transpose + quantize: in [R,C] fp32 -> q1/q2 [C,R] s8
__global__ void quant_f32_T(const float* __restrict__ in,
                            int8_t* __restrict__ q1, int8_t* __restrict__ q2,
                            int R, int C, int slot)
{
    __shared__ float t[32][33];
    const int c0 = blockIdx.x * 32, r0 = blockIdx.y * 32;
    const int tx = threadIdx.x, ty = threadIdx.y;
    #pragma unroll
    for (int k = 0; k < 4; k++)
        t[ty + 8 * k][tx] = in[(size_t)(r0 + ty + 8 * k) * C + c0 + tx];
    __syncthreads();
    const float inv = 1.0f / dscale(slot);
    #pragma unroll
    for (int k = 0; k < 4; k++) {
        float a = t[tx][ty + 8 * k] * inv;
        int8_t c1 = clamp_q1(a);
        size_t o = (size_t)(c0 + ty + 8 * k) * R + r0 + tx;
        q1[o] = c1;
        q2[o] = (int8_t)__float2int_rn((a - (float)c1) * 128.0f);
    }
}

// XH transpose: reads XH = hi + lo/2048 at rows [MROWS + b*SEQ + s], writes hi-only ^T
__global__ void txsplit_kernel(const h16* __restrict__ qh, const h16* __restrict__ ql,
                               h16* __restrict__ oh)
{
    __shared__ float t[32][33];
    const int z = blockIdx.z;
    const int d0 = blockIdx.x * 32, s0 = blockIdx.y * 32;
    const int tx = threadIdx.x, ty = threadIdx.y;
    #pragma unroll
    for (int k = 0; k < 4; k++) {
        size_t idx = (size_t)(MROWS + z * SEQ + s0 + ty + 8 * k) * DM + d0 + tx;
        t[ty + 8 * k][tx] = __half2float(qh[idx]) + __half2float(ql[idx]) * INV_LO;
    }
    __syncthreads();
    #pragma unroll
    for (int k = 0; k < 4; k++) {
        size_t o = (size_t)z * DM * SEQ + (size_t)(d0 + ty + 8 * k) * SEQ + s0 + tx;
        oh[o] = __float2half_rn(t[tx][ty + 8 * k]);
    }
}

__global__ void wkbq_kernel(const float* __restrict__ Wk, const float* __restrict__ bq,
                            float* __restrict__ w2)
{
    int w = (blockIdx.x * blockDim.x + threadIdx.x) >> 5;
    int lane = threadIdx.x & 31;
    if (w >= DM) return;
    float s = 0.f;
    for (int e = lane; e < DM; e += 32) s += Wk[(size_t)w * DM + e] * bq[e];
    #pragma unroll
    for (int o = 16; o > 0; o >>= 1) s += __shfl_down_sync(0xffffffffu, s, o);
    if (lane == 0) w2[w] = s;
}

__global__ void rb_kernel(const float* __restrict__ Wo, const float* __restrict__ bv,
                          const float* __restrict__ bo, float* __restrict__ rb)
{
    int d = blockIdx.x * blockDim.x + threadIdx.x;
    if (d >= DM) return;
    float s = 0.f;
    for (int e = 0; e < DM; e++) s += bv[e] * Wo[(size_t)e * DM + d];
    rb[d] = s + bo[d];
}

__global__ void vvec_kernel(const float* __restrict__ x, const float* __restrict__ w2,
                            float* __restrict__ v)
{
    int w = (blockIdx.x * blockDim.x + threadIdx.x) >> 5;
    int lane = threadIdx.x & 31;
    if (w >= MROWS) return;
    float s = 0.f;
    for (int d = lane; d < DM; d += 32) s += x[(size_t)w * DM + d] * w2[d];
    #pragma unroll
    for (int o = 16; o > 0; o >>= 1) s += __shfl_down_sync(0xffffffffu, s, o);
    if (lane == 0) v[w] = s;
}

__global__ __launch_bounds__(256)
void softmax_split_kernel(float* __restrict__ P, const float* __restrict__ V,
                          h16* __restrict__ Ph, h16* __restrict__ Pl)
{
    const int rowi = blockIdx.x;
    const int b = rowi / SEQ, q = rowi % SEQ;
    const size_t off = (size_t)b * SEQ * SEQ + (size_t)q * SEQ;
    float* p = P + off;
    const float* vv = V + (size_t)b * SEQ;
    h16* ph = Ph + off;
    h16* pl = Pl + off;
    const int n = q + 1;

    __shared__ float red[256];
    const int tid = threadIdx.x;

    float mx = -CUDART_INF_F;
    for (int k = tid; k < n; k += 256) mx = fmaxf(mx, p[k] + 0.125f * vv[k]);
    red[tid] = mx; __syncthreads();
    #pragma unroll
    for (int s = 128; s > 0; s >>= 1) {
        if (tid < s) red[tid] = fmaxf(red[tid], red[tid + s]);
        __syncthreads();
    }
    mx = red[0]; __syncthreads();

    float sum = 0.f;
    for (int k = tid; k < n; k += 256) {
        float e = expf(p[k] + 0.125f * vv[k] - mx);
        p[k] = e;
        sum += e;
    }
    red[tid] = sum; __syncthreads();
    #pragma unroll
    for (int s = 128; s > 0; s >>= 1) {
        if (tid < s) red[tid] += red[tid + s];
        __syncthreads();
    }
    const float inv = 1.f / red[0];

    for (int k = tid; k < n; k += 256) {
        float w = p[k] * inv;
        h16 h = __float2half_rn(w);
        ph[k] = h;
        pl[k] = __float2half_rn((w - __half2float(h)) * LO_SCALE);
    }
    const int fillEnd = ((q >> 7) + 1) << 7;
    for (int k = n + tid; k < fillEnd; k += 256) {
        ph[k] = __float2half_rn(0.f);
        pl[k] = __float2half_rn(0.f);
    }
}

// ============================================================================
extern "C" void kernel_launch(void* const* d_in, const int*, int, void* d_out, int)
{
    const float* x  = (const float*)d_in[0];
    const float* Wq = (const float*)d_in[1];
    const float* bq = (const float*)d_in[2];
    const float* Wk = (const float*)d_in[3];
    const float* bk = (const float*)d_in[4];   (void)bk;  // cancels in softmax
    const float* Wv = (const float*)d_in[5];
    const float* bv = (const float*)d_in[6];
    const float* Wo = (const float*)d_in[7];
    const float* bo = (const float*)d_in[8];
    float* out = (float*)d_out;

    int8_t *x1, *x2, *wa1, *wa2, *wb1, *wb2, *gg1, *gg2, *qg1, *qg2;
    h16 *gh, *gl, *qxh, *qxl, *xth, *phh, *pll;
    float *p, *w2, *v, *rb;
    cudaGetSymbolAddress((void**)&x1,  g_x1);  cudaGetSymbolAddress((void**)&x2,  g_x2);
    cudaGetSymbolAddress((void**)&wa1, g_wa1); cudaGetSymbolAddress((void**)&wa2, g_wa2);
    cudaGetSymbolAddress((void**)&wb1, g_wb1); cudaGetSymbolAddress((void**)&wb2, g_wb2);
    cudaGetSymbolAddress((void**)&gg1, g_g1);  cudaGetSymbolAddress((void**)&gg2, g_g2);
    cudaGetSymbolAddress((void**)&qg1, g_qg1); cudaGetSymbolAddress((void**)&qg2, g_qg2);
    cudaGetSymbolAddress((void**)&gh,  g_gh);  cudaGetSymbolAddress((void**)&gl,  g_gl);
    cudaGetSymbolAddress((void**)&qxh, g_qxh); cudaGetSymbolAddress((void**)&qxl, g_qxl);
    cudaGetSymbolAddress((void**)&xth, g_xth);
    cudaGetSymbolAddress((void**)&p,   g_p);
    cudaGetSymbolAddress((void**)&phh, g_ph);  cudaGetSymbolAddress((void**)&pll, g_pl);
    cudaGetSymbolAddress((void**)&w2,  g_w2);  cudaGetSymbolAddress((void**)&v,   g_v);
    cudaGetSymbolAddress((void**)&rb,  g_rb);

    cudaFuncSetAttribute(tc_gemm_i8<1, false>, cudaFuncAttributeMaxDynamicSharedMemorySize, SMEM_DYN);
    cudaFuncSetAttribute(tc_gemm_i8<0, true>,  cudaFuncAttributeMaxDynamicSharedMemorySize, SMEM_DYN);
    cudaFuncSetAttribute(tc_gemm_pv,           cudaFuncAttributeMaxDynamicSharedMemorySize, SMEM_DYN);

    // ---- scalar/bias prep ------------------------------------------------------
    wkbq_kernel<<<DM * 32 / 256, 256>>>(Wk, bq, w2);
    rb_kernel<<<DM / 256, 256>>>(Wo, bv, bo, rb);
    vvec_kernel<<<MROWS * 32 / 256, 256>>>(x, w2, v);

    // ---- maxabs + quantize inputs (slots: 0:x 1:Wk 2:WoT 3:Wq 4:Wv) ------------
    maxabs_f32<<<148, 256>>>(x,  MROWS * DM, 0);
    maxabs_f32<<<64,  256>>>(Wk, DM * DM, 1);
    maxabs_f32<<<64,  256>>>(Wo, DM * DM, 2);
    maxabs_f32<<<64,  256>>>(Wq, DM * DM, 3);
    maxabs_f32<<<64,  256>>>(Wv, DM * DM, 4);
    quant_f32<<<(MROWS * DM + 255) / 256, 256>>>(x,  x1, x2, MROWS * DM, 0);
    quant_f32<<<(DM * DM + 255) / 256, 256>>>(Wk, wa1,           wa2,           DM * DM, 1);
    quant_f32<<<(DM * DM + 255) / 256, 256>>>(Wq, wb1,           wb2,           DM * DM, 3);
    quant_f32<<<(DM * DM + 255) / 256, 256>>>(Wv, wb1 + DM * DM, wb2 + DM * DM, DM * DM, 4);
    {
        dim3 blk(32, 8), grid(DM / 32, DM / 32);
        quant_f32_T<<<grid, blk>>>(Wo, wa1 + DM * DM, wa2 + DM * DM, DM, DM, 2);
    }

    // ---- GT = Wk*Wq^T ; HT = WoT*Wv^T (int8, z=2) -> f16 limbs -----------------
    {
        dim3 grid(DM / TN, DM / TM, 2), blk(256);
        tc_gemm_i8<1, false><<<grid, blk, SMEM_DYN>>>(
            wa1, wa2, wb1, wb2, nullptr, gh, gl,
            DM, DM, DM, DM, 1.f,
            (size_t)DM * DM, (size_t)DM * DM, (size_t)DM * DM,
            1, 1, 3, 1);
    }
    // quantize GT/HT (slots 5,6)
    maxabs_h2<<<64, 256>>>(gh, gl, 0,                  DM * DM, 5);
    maxabs_h2<<<64, 256>>>(gh, gl, (size_t)DM * DM,    DM * DM, 6);
    quant_h2<<<(DM * DM + 255) / 256, 256>>>(gh, gl, 0,               gg1,           gg2,           DM * DM, 5);
    quant_h2<<<(DM * DM + 255) / 256, 256>>>(gh, gl, (size_t)DM * DM, gg1 + DM * DM, gg2 + DM * DM, DM * DM, 6);

    // ---- QG = x*GT ; XH = x*HT (int8, z=2) -> f16 limbs ------------------------
    {
        dim3 grid(DM / TN, MROWS / TM, 2), blk(256);
        tc_gemm_i8<1, false><<<grid, blk, SMEM_DYN>>>(
            x1, x2, gg1, gg2, nullptr, qxh, qxl,
            DM, DM, DM, DM, 1.f,
            0, (size_t)DM * DM, (size_t)MROWS * DM,
            0, 0, 5, 1);
    }
    // quantize QG slice (slot 7)
    maxabs_h2<<<148, 256>>>(qxh, qxl, 0, MROWS * DM, 7);
    quant_h2<<<(MROWS * DM + 255) / 256, 256>>>(qxh, qxl, 0, qg1, qg2, MROWS * DM, 7);

    // ---- scores = 0.125 * QG @ x^T (int8, causal, fp32 out) --------------------
    {
        dim3 grid(SEQ / TN, SEQ / TM, BATCH), blk(256);
        tc_gemm_i8<0, true><<<grid, blk, SMEM_DYN>>>(
            qg1, qg2, x1, x2, p, nullptr, nullptr,
            DM, DM, DM, SEQ, 0.125f,
            (size_t)SEQ * DM, (size_t)SEQ * DM, (size_t)SEQ * SEQ,
            7, 0, 0, 0);
    }

    // ---- XH transpose (hi only; PV uses 2-term with B-hi) -----------------------
    {
        dim3 blk(32, 8), grid(DM / 32, SEQ / 32, BATCH);
        txsplit_kernel<<<grid, blk>>>(qxh, qxl, xth);
    }

    // ---- softmax over (scores + 0.125*v[j]) -> f16 limb weights -----------------
    softmax_split_kernel<<<MROWS, 256>>>(p, v, phh, pll);

    // ---- out = P @ XH + (bv*Wo + bo)  (f16 path, writes d_out) ------------------
    {
        dim3 grid(DM / TN, SEQ / TM, BATCH), blk(256);
        tc_gemm_pv<<<grid, blk, SMEM_DYN>>>(
            phh, pll, xth, rb, out,
            SEQ, SEQ, DM,
            (size_t)SEQ * SEQ, (size_t)DM * SEQ, (size_t)SEQ * DM);
    }
}

// round 13
// speedup vs baseline: 2.7334x; 2.7334x over previous
#include <cuda_runtime.h>
#include <cuda_fp16.h>
#include <math_constants.h>
#include <stdint.h>

#define BATCH 4
#define SEQ   2048
#define DM    1024
#define MROWS (BATCH * SEQ)

#define LO_SCALE  2048.0f
#define INV_LO    (1.0f / 2048.0f)

// ---- GEMM tiling (proven 256-thread / 8-warp config) --------------------------
#define TM 128
#define TN 128
#define BK 64                         // f16 elems per K-chunk (128 bytes/row)
#define TILE_BYTES (128 * 128)        // 16 KB per operand tile
#define STAGE_BYTES (4 * TILE_BYTES)  // Ahi,Alo,Bhi,Blo = 64 KB
#define NSTAGE 3
#define SMEM_DYN (NSTAGE * STAGE_BYTES)   // 192 KB

typedef __half h16;

// ---- scratch (static __device__: allocation-free) ------------------------------
#define AL1K __align__(1024)
__device__ AL1K h16   g_xh [MROWS * DM];
__device__ AL1K h16   g_xl [MROWS * DM];
__device__ AL1K h16   g_wAh[2 * DM * DM];   // [Wk ; Wo^T] split hi
__device__ AL1K h16   g_wAl[2 * DM * DM];
__device__ AL1K h16   g_wBh[2 * DM * DM];   // [Wq ; Wv] split hi
__device__ AL1K h16   g_wBl[2 * DM * DM];
__device__ AL1K h16   g_gh [2 * DM * DM];   // [GT ; HT] split hi
__device__ AL1K h16   g_gl [2 * DM * DM];
__device__ AL1K h16   g_qxh[(size_t)2 * MROWS * DM];  // [QG ; XH] split hi
__device__ AL1K h16   g_qxl[(size_t)2 * MROWS * DM];
__device__ AL1K h16   g_xth[MROWS * DM];    // XH^T per batch [B][D][S]
__device__ AL1K h16   g_xtl[MROWS * DM];
__device__ AL1K float g_p  [(size_t)BATCH * SEQ * SEQ];
__device__ AL1K h16   g_ph [(size_t)BATCH * SEQ * SEQ];
__device__ AL1K h16   g_pl [(size_t)BATCH * SEQ * SEQ];
__device__ AL1K float g_w2 [DM];
__device__ AL1K float g_v  [MROWS];
__device__ AL1K float g_rb [DM];

// ---- PTX helpers -----------------------------------------------------------------
__device__ __forceinline__ uint32_t s2u(const void* p) {
    uint32_t a;
    asm("{ .reg .u64 t; cvta.to.shared.u64 t, %1; cvt.u32.u64 %0, t; }" : "=r"(a) : "l"(p));
    return a;
}
__device__ __forceinline__ void cp16(uint32_t saddr, const void* gaddr) {
    asm volatile("cp.async.cg.shared.global [%0], [%1], 16;" :: "r"(saddr), "l"(gaddr));
}
__device__ __forceinline__ void cp_commit() { asm volatile("cp.async.commit_group;"); }
__device__ __forceinline__ void cp_wait2()  { asm volatile("cp.async.wait_group 2;" ::: "memory"); }

__device__ __forceinline__ void ldm4(uint32_t* r, uint32_t addr) {
    asm volatile("ldmatrix.sync.aligned.m8n8.x4.shared.b16 {%0,%1,%2,%3}, [%4];"
                 : "=r"(r[0]), "=r"(r[1]), "=r"(r[2]), "=r"(r[3]) : "r"(addr));
}
__device__ __forceinline__ void mma_f32(float* c, const uint32_t* a, const uint32_t* b) {
    asm volatile(
        "mma.sync.aligned.m16n8k16.row.col.f32.f16.f16.f32 "
        "{%0,%1,%2,%3}, {%4,%5,%6,%7}, {%8,%9}, {%0,%1,%2,%3};"
        : "+f"(c[0]), "+f"(c[1]), "+f"(c[2]), "+f"(c[3])
        : "r"(a[0]), "r"(a[1]), "r"(a[2]), "r"(a[3]), "r"(b[0]), "r"(b[1]));
}
__device__ __forceinline__ void mma_f16(uint32_t* c, const uint32_t* a, const uint32_t* b) {
    asm volatile(
        "mma.sync.aligned.m16n8k16.row.col.f16.f16.f16.f16 "
        "{%0,%1}, {%2,%3,%4,%5}, {%6,%7}, {%0,%1};"
        : "+r"(c[0]), "+r"(c[1])
        : "r"(a[0]), "r"(a[1]), "r"(a[2]), "r"(a[3]), "r"(b[0]), "r"(b[1]));
}
__device__ __forceinline__ uint32_t pk2(float a, float b) {
    __half2 t = __floats2half2_rn(a, b);
    return *reinterpret_cast<uint32_t*>(&t);
}

// ============================================================================
// Tensor-core GEMM, 256 threads, 8 warps, warp tile 32x64 (proven config).
//   C[M,N] = scale*((Ahi+Alo/2048)[M,K] @ ((Bhi+Blo/2048)[N,K])^T)+bias
//   NTERM=3: AhBh(f32) + AhBl(f16) + AlBh(f16)
//   NTERM=2: AhBh(f32) + AlBh(f16)   (B-lo tile never loaded)
//   NTERM=1: AhBh(f32) only          (A-lo and B-lo never loaded)
//   OUTMODE 0: fp32 out. OUTMODE 1: f16 split out (lo x2048).
//   CAUSAL: skip tiles above diagonal.  PVLIM: K truncated.  REVY: heavy first.
// ============================================================================
template<int OUTMODE, bool HAS_BIAS, bool CAUSAL, bool PVLIM, bool REVY, int NTERM>
__global__ __launch_bounds__(256, 1)
void tc_gemm(const h16* __restrict__ Ah, const h16* __restrict__ Al,
             const h16* __restrict__ Bh, const h16* __restrict__ Bl,
             const float* __restrict__ bias,
             float* __restrict__ Cf, h16* __restrict__ Ch, h16* __restrict__ Cl,
             int Kfull, int ldA, int ldB, int ldC, float scale,
             size_t sA, size_t sB, size_t sC)
{
    const int bmi = REVY ? (gridDim.y - 1 - blockIdx.y) : blockIdx.y;
    const int m0 = bmi * TM;
    const int n0 = blockIdx.x * TN;
    if (CAUSAL && n0 > m0) return;

    const int z = blockIdx.z;
    Ah += (size_t)z * sA;  Al += (size_t)z * sA;
    Bh += (size_t)z * sB;  Bl += (size_t)z * sB;

    extern __shared__ char dsm[];
    const uint32_t smem = s2u(dsm);

    const int tid  = threadIdx.x;
    const int wid  = tid >> 5;
    const int lane = tid & 31;
    const int wm   = wid & 3;    // 4 warp-rows  (32 M each)
    const int wn   = wid >> 2;   // 2 warp-cols  (64 N each)

    const int nchunk = PVLIM ? (m0 + TM) / BK : Kfull / BK;

    // ---- loader: each thread = half a row (4x16B segs) of each tile -----------
    const int lrow = tid >> 1;            // 0..127
    const int sb   = (tid & 1) * 4;       // seg base 0 or 4
    const char* gp[4];
    uint32_t    so[4][4];
    {
        const h16* bases[4] = {Ah, Al, Bh, Bl};
        #pragma unroll
        for (int t = 0; t < 4; t++) {
            const int off = (t < 2) ? m0 : n0;
            const int ld  = (t < 2) ? ldA : ldB;
            gp[t] = (const char*)(bases[t] + (size_t)(off + lrow) * ld);
            #pragma unroll
            for (int j = 0; j < 4; j++) {
                const int seg = sb + j;
                so[t][j] = (uint32_t)(t * TILE_BYTES + lrow * 128 +
                                      ((seg ^ (lrow & 7)) << 4));
            }
        }
    }

    auto load_stage = [&](int slot, int chunk) {
        if (chunk < nchunk) {
            const uint32_t s0 = smem + slot * STAGE_BYTES;
            const size_t goff = (size_t)chunk * 128;
            #pragma unroll
            for (int t = 0; t < 4; t++) {
                if (t == 1 && NTERM < 2) continue;   // A-lo unused
                if (t == 3 && NTERM < 3) continue;   // B-lo unused
                #pragma unroll
                for (int j = 0; j < 4; j++)
                    cp16(s0 + so[t][j], gp[t] + goff + (size_t)(sb + j) * 16);
            }
        }
        cp_commit();
    };

    float    accf[2][8][4];
    uint32_t acch[2][8][2];
    #pragma unroll
    for (int a = 0; a < 2; a++)
        #pragma unroll
        for (int b = 0; b < 8; b++) {
            #pragma unroll
            for (int c = 0; c < 4; c++) accf[a][b][c] = 0.f;
            acch[a][b][0] = 0u; acch[a][b][1] = 0u;
        }

    load_stage(0, 0);
    load_stage(1, 1);
    load_stage(2, 2);

    const int a_r  = lane & 15;
    const int a_kh = lane >> 4;
    const int b_nl = ((lane >> 4) & 1) * 8 + (lane & 7);
    const int b_kh = (lane >> 3) & 1;

    for (int i = 0; i < nchunk; i++) {
        cp_wait2();
        __syncthreads();
        const uint32_t s0 = smem + (i % 3) * STAGE_BYTES;

        #pragma unroll
        for (int kk = 0; kk < 4; kk++) {
            uint32_t ahf[2][4], alf[2][4], bhf[4][4], blf[4][4];
            #pragma unroll
            for (int mt = 0; mt < 2; mt++) {
                const int row = wm * 32 + mt * 16 + a_r;
                const int seg = kk * 2 + a_kh;
                const uint32_t off = (uint32_t)(row * 128 + ((seg ^ (row & 7)) << 4));
                ldm4(ahf[mt], s0 + 0 * TILE_BYTES + off);
                if (NTERM >= 2) ldm4(alf[mt], s0 + 1 * TILE_BYTES + off);
            }
            #pragma unroll
            for (int p = 0; p < 4; p++) {
                const int row = wn * 64 + p * 16 + b_nl;
                const int seg = kk * 2 + b_kh;
                const uint32_t off = (uint32_t)(row * 128 + ((seg ^ (row & 7)) << 4));
                ldm4(bhf[p], s0 + 2 * TILE_BYTES + off);
                if (NTERM >= 3) ldm4(blf[p], s0 + 3 * TILE_BYTES + off);
            }
            // main term (f32 acc)
            #pragma unroll
            for (int mt = 0; mt < 2; mt++)
                #pragma unroll
                for (int nt = 0; nt < 8; nt++)
                    mma_f32(accf[mt][nt], ahf[mt], &bhf[nt >> 1][(nt & 1) * 2]);
            // correction terms (f16 acc; lo operands pre-scaled x2048)
            if (NTERM >= 3) {
                #pragma unroll
                for (int mt = 0; mt < 2; mt++)
                    #pragma unroll
                    for (int nt = 0; nt < 8; nt++)
                        mma_f16(acch[mt][nt], ahf[mt], &blf[nt >> 1][(nt & 1) * 2]);
            }
            if (NTERM >= 2) {
                #pragma unroll
                for (int mt = 0; mt < 2; mt++)
                    #pragma unroll
                    for (int nt = 0; nt < 8; nt++)
                        mma_f16(acch[mt][nt], alf[mt], &bhf[nt >> 1][(nt & 1) * 2]);
            }
        }
        __syncthreads();
        load_stage(i % 3, i + 3);
    }

    #pragma unroll
    for (int mt = 0; mt < 2; mt++) {
        #pragma unroll
        for (int h = 0; h < 2; h++) {
            const int row = m0 + wm * 32 + mt * 16 + (lane >> 2) + 8 * h;
            #pragma unroll
            for (int nt = 0; nt < 8; nt++) {
                const int col = n0 + wn * 64 + nt * 8 + (lane & 3) * 2;
                float c0 = 0.f, c1 = 0.f;
                if (NTERM >= 2) {
                    const __half2 hc = *reinterpret_cast<const __half2*>(&acch[mt][nt][h]);
                    c0 = __low2float(hc)  * INV_LO;
                    c1 = __high2float(hc) * INV_LO;
                }
                float v0 = (accf[mt][nt][2 * h + 0] + c0) * scale;
                float v1 = (accf[mt][nt][2 * h + 1] + c1) * scale;
                if (HAS_BIAS) {
                    const float2 bb = *reinterpret_cast<const float2*>(bias + col);
                    v0 += bb.x; v1 += bb.y;
                }
                if (OUTMODE == 0) {
                    *reinterpret_cast<float2*>(
                        Cf + (size_t)z * sC + (size_t)row * ldC + col) =
                        make_float2(v0, v1);
                } else {
                    float h0 = __half2float(__float2half_rn(v0));
                    float h1 = __half2float(__float2half_rn(v1));
                    *reinterpret_cast<uint32_t*>(
                        Ch + (size_t)z * sC + (size_t)row * ldC + col) = pk2(h0, h1);
                    *reinterpret_cast<uint32_t*>(
                        Cl + (size_t)z * sC + (size_t)row * ldC + col) =
                        pk2((v0 - h0) * LO_SCALE, (v1 - h1) * LO_SCALE);
                }
            }
        }
    }
}

// ============================================================================
// prep kernels (all lo outputs pre-scaled x2048)
// ============================================================================
__global__ void split_kernel(const float* __restrict__ in,
                             h16* __restrict__ oh, h16* __restrict__ ol, int n)
{
    int i = blockIdx.x * blockDim.x + threadIdx.x;
    if (i >= n) return;
    float v = in[i];
    h16 h = __float2half_rn(v);
    oh[i] = h;
    ol[i] = __float2half_rn((v - __half2float(h)) * LO_SCALE);
}

__global__ void tsplit_kernel(const float* __restrict__ in,
                              h16* __restrict__ oh, h16* __restrict__ ol,
                              int R, int C)
{
    __shared__ float t[32][33];
    const int c0 = blockIdx.x * 32, r0 = blockIdx.y * 32;
    const int tx = threadIdx.x, ty = threadIdx.y;
    #pragma unroll
    for (int k = 0; k < 4; k++)
        t[ty + 8 * k][tx] = in[(size_t)(r0 + ty + 8 * k) * C + c0 + tx];
    __syncthreads();
    #pragma unroll
    for (int k = 0; k < 4; k++) {
        float v = t[tx][ty + 8 * k];
        h16 h = __float2half_rn(v);
        size_t o = (size_t)(c0 + ty + 8 * k) * R + r0 + tx;
        oh[o] = h;
        ol[o] = __float2half_rn((v - __half2float(h)) * LO_SCALE);
    }
}

// XH transpose+split: reads XH = hi + lo/2048 at rows [MROWS + b*SEQ + s], ld=DM
__global__ void txsplit_kernel(const h16* __restrict__ qh, const h16* __restrict__ ql,
                               h16* __restrict__ oh, h16* __restrict__ ol)
{
    __shared__ float t[32][33];
    const int z = blockIdx.z;
    const int d0 = blockIdx.x * 32, s0 = blockIdx.y * 32;
    const int tx = threadIdx.x, ty = threadIdx.y;
    #pragma unroll
    for (int k = 0; k < 4; k++) {
        size_t idx = (size_t)(MROWS + z * SEQ + s0 + ty + 8 * k) * DM + d0 + tx;
        t[ty + 8 * k][tx] = __half2float(qh[idx]) + __half2float(ql[idx]) * INV_LO;
    }
    __syncthreads();
    #pragma unroll
    for (int k = 0; k < 4; k++) {
        float v = t[tx][ty + 8 * k];
        h16 h = __float2half_rn(v);
        size_t o = (size_t)z * DM * SEQ + (size_t)(d0 + ty + 8 * k) * SEQ + s0 + tx;
        oh[o] = h;
        ol[o] = __float2half_rn((v - __half2float(h)) * LO_SCALE);
    }
}

__global__ void wkbq_kernel(const float* __restrict__ Wk, const float* __restrict__ bq,
                            float* __restrict__ w2)
{
    int w = (blockIdx.x * blockDim.x + threadIdx.x) >> 5;
    int lane = threadIdx.x & 31;
    if (w >= DM) return;
    float s = 0.f;
    for (int e = lane; e < DM; e += 32) s += Wk[(size_t)w * DM + e] * bq[e];
    #pragma unroll
    for (int o = 16; o > 0; o >>= 1) s += __shfl_down_sync(0xffffffffu, s, o);
    if (lane == 0) w2[w] = s;
}

__global__ void rb_kernel(const float* __restrict__ Wo, const float* __restrict__ bv,
                          const float* __restrict__ bo, float* __restrict__ rb)
{
    int d = blockIdx.x * blockDim.x + threadIdx.x;
    if (d >= DM) return;
    float s = 0.f;
    for (int e = 0; e < DM; e++) s += bv[e] * Wo[(size_t)e * DM + d];
    rb[d] = s + bo[d];
}

__global__ void vvec_kernel(const float* __restrict__ x, const float* __restrict__ w2,
                            float* __restrict__ v)
{
    int w = (blockIdx.x * blockDim.x + threadIdx.x) >> 5;
    int lane = threadIdx.x & 31;
    if (w >= MROWS) return;
    float s = 0.f;
    for (int d = lane; d < DM; d += 32) s += x[(size_t)w * DM + d] * w2[d];
    #pragma unroll
    for (int o = 16; o > 0; o >>= 1) s += __shfl_down_sync(0xffffffffu, s, o);
    if (lane == 0) v[w] = s;
}

__global__ __launch_bounds__(256)
void softmax_split_kernel(float* __restrict__ P, const float* __restrict__ V,
                          h16* __restrict__ Ph, h16* __restrict__ Pl)
{
    const int rowi = blockIdx.x;
    const int b = rowi / SEQ, q = rowi % SEQ;
    const size_t off = (size_t)b * SEQ * SEQ + (size_t)q * SEQ;
    float* p = P + off;
    const float* vv = V + (size_t)b * SEQ;
    h16* ph = Ph + off;
    h16* pl = Pl + off;
    const int n = q + 1;

    __shared__ float red[256];
    const int tid = threadIdx.x;

    float mx = -CUDART_INF_F;
    for (int k = tid; k < n; k += 256) mx = fmaxf(mx, p[k] + 0.125f * vv[k]);
    red[tid] = mx; __syncthreads();
    #pragma unroll
    for (int s = 128; s > 0; s >>= 1) {
        if (tid < s) red[tid] = fmaxf(red[tid], red[tid + s]);
        __syncthreads();
    }
    mx = red[0]; __syncthreads();

    float sum = 0.f;
    for (int k = tid; k < n; k += 256) {
        float e = expf(p[k] + 0.125f * vv[k] - mx);
        p[k] = e;
        sum += e;
    }
    red[tid] = sum; __syncthreads();
    #pragma unroll
    for (int s = 128; s > 0; s >>= 1) {
        if (tid < s) red[tid] += red[tid + s];
        __syncthreads();
    }
    const float inv = 1.f / red[0];

    for (int k = tid; k < n; k += 256) {
        float w = p[k] * inv;
        h16 h = __float2half_rn(w);
        ph[k] = h;
        pl[k] = __float2half_rn((w - __half2float(h)) * LO_SCALE);
    }
    const int fillEnd = ((q >> 7) + 1) << 7;
    for (int k = n + tid; k < fillEnd; k += 256) {
        ph[k] = __float2half_rn(0.f);
        pl[k] = __float2half_rn(0.f);
    }
}

// ============================================================================
extern "C" void kernel_launch(void* const* d_in, const int*, int, void* d_out, int)
{
    const float* x  = (const float*)d_in[0];
    const float* Wq = (const float*)d_in[1];
    const float* bq = (const float*)d_in[2];
    const float* Wk = (const float*)d_in[3];
    const float* bk = (const float*)d_in[4];   (void)bk;  // cancels in softmax
    const float* Wv = (const float*)d_in[5];
    const float* bv = (const float*)d_in[6];
    const float* Wo = (const float*)d_in[7];
    const float* bo = (const float*)d_in[8];
    float* out = (float*)d_out;

    h16 *xh, *xl, *wAh, *wAl, *wBh, *wBl, *gh, *gl, *qxh, *qxl, *xth, *xtl, *phh, *pll;
    float *p, *w2, *v, *rb;
    cudaGetSymbolAddress((void**)&xh,  g_xh);  cudaGetSymbolAddress((void**)&xl,  g_xl);
    cudaGetSymbolAddress((void**)&wAh, g_wAh); cudaGetSymbolAddress((void**)&wAl, g_wAl);
    cudaGetSymbolAddress((void**)&wBh, g_wBh); cudaGetSymbolAddress((void**)&wBl, g_wBl);
    cudaGetSymbolAddress((void**)&gh,  g_gh);  cudaGetSymbolAddress((void**)&gl,  g_gl);
    cudaGetSymbolAddress((void**)&qxh, g_qxh); cudaGetSymbolAddress((void**)&qxl, g_qxl);
    cudaGetSymbolAddress((void**)&xth, g_xth); cudaGetSymbolAddress((void**)&xtl, g_xtl);
    cudaGetSymbolAddress((void**)&p,   g_p);
    cudaGetSymbolAddress((void**)&phh, g_ph);  cudaGetSymbolAddress((void**)&pll, g_pl);
    cudaGetSymbolAddress((void**)&w2,  g_w2);  cudaGetSymbolAddress((void**)&v,   g_v);
    cudaGetSymbolAddress((void**)&rb,  g_rb);

    cudaFuncSetAttribute(tc_gemm<1, false, false, false, false, 3>, cudaFuncAttributeMaxDynamicSharedMemorySize, SMEM_DYN);
    cudaFuncSetAttribute(tc_gemm<1, false, false, false, false, 2>, cudaFuncAttributeMaxDynamicSharedMemorySize, SMEM_DYN);
    cudaFuncSetAttribute(tc_gemm<1, false, false, false, false, 1>, cudaFuncAttributeMaxDynamicSharedMemorySize, SMEM_DYN);
    cudaFuncSetAttribute(tc_gemm<0, false, true,  false, false, 2>, cudaFuncAttributeMaxDynamicSharedMemorySize, SMEM_DYN);
    cudaFuncSetAttribute(tc_gemm<0, true,  false, true,  true,  2>, cudaFuncAttributeMaxDynamicSharedMemorySize, SMEM_DYN);

    // ---- prep: splits + bias vectors ---------------------------------------
    split_kernel<<<(MROWS * DM + 255) / 256, 256>>>(x, xh, xl, MROWS * DM);
    split_kernel<<<(DM * DM + 255) / 256, 256>>>(Wk, wAh,           wAl,           DM * DM);
    split_kernel<<<(DM * DM + 255) / 256, 256>>>(Wq, wBh,           wBl,           DM * DM);
    split_kernel<<<(DM * DM + 255) / 256, 256>>>(Wv, wBh + DM * DM, wBl + DM * DM, DM * DM);
    {
        dim3 blk(32, 8), grid(DM / 32, DM / 32);
        tsplit_kernel<<<grid, blk>>>(Wo, wAh + DM * DM, wAl + DM * DM, DM, DM);
    }
    wkbq_kernel<<<DM * 32 / 256, 256>>>(Wk, bq, w2);
    rb_kernel<<<DM / 256, 256>>>(Wo, bv, bo, rb);
    vvec_kernel<<<MROWS * 32 / 256, 256>>>(x, w2, v);

    // ---- GT = Wk*Wq^T ; HT = Wo^T*Wv^T-form (z=2, FULL 3-term: error-amplified)
    {
        dim3 grid(DM / TN, DM / TM, 2), blk(256);
        tc_gemm<1, false, false, false, false, 3><<<grid, blk, SMEM_DYN>>>(
            wAh, wAl, wBh, wBl, nullptr, nullptr, gh, gl,
            DM, DM, DM, DM, 1.f,
            (size_t)DM * DM, (size_t)DM * DM, (size_t)DM * DM);
    }

    // ---- QG = x*GT (2-term: logit path needs precision) ------------------------
    {
        dim3 grid(DM / TN, MROWS / TM, 1), blk(256);
        tc_gemm<1, false, false, false, false, 2><<<grid, blk, SMEM_DYN>>>(
            xh, xl, gh, gl, nullptr, nullptr, qxh, qxl,
            DM, DM, DM, DM, 1.f, 0, 0, 0);
    }

    // ---- XH = x*HT (1-term: consumed as 11-bit B operand by P@V) ---------------
    {
        dim3 grid(DM / TN, MROWS / TM, 1), blk(256);
        tc_gemm<1, false, false, false, false, 1><<<grid, blk, SMEM_DYN>>>(
            xh, xl, gh + (size_t)DM * DM, gl + (size_t)DM * DM,
            nullptr, nullptr, qxh + (size_t)MROWS * DM, qxl + (size_t)MROWS * DM,
            DM, DM, DM, DM, 1.f, 0, 0, 0);
    }

    // ---- scores core = 0.125 * QG @ x^T (causal, 2-term: drop QGh*xl) ----------
    {
        dim3 grid(SEQ / TN, SEQ / TM, BATCH), blk(256);
        tc_gemm<0, false, true, false, false, 2><<<grid, blk, SMEM_DYN>>>(
            qxh, qxl, xh, xl, nullptr, p, nullptr, nullptr,
            DM, DM, DM, SEQ, 0.125f,
            (size_t)SEQ * DM, (size_t)SEQ * DM, (size_t)SEQ * SEQ);
    }

    // ---- XH transpose+split: [B][S][D] -> [B][D][S] ------------------------------
    {
        dim3 blk(32, 8), grid(DM / 32, SEQ / 32, BATCH);
        txsplit_kernel<<<grid, blk>>>(qxh, qxl, xth, xtl);
    }

    // ---- softmax over (scores + 0.125*v[j]) -> split f16 weights -----------------
    softmax_split_kernel<<<MROWS, 256>>>(p, v, phh, pll);

    // ---- out = P @ XH + (bv*Wo + bo)  (2-term: drop Ph*XHl) -----------------------
    {
        dim3 grid(DM / TN, SEQ / TM, BATCH), blk(256);
        tc_gemm<0, true, false, true, true, 2><<<grid, blk, SMEM_DYN>>>(
            phh, pll, xth, xtl, rb, out, nullptr, nullptr,
            SEQ, SEQ, SEQ, DM, 1.f,
            (size_t)SEQ * SEQ, (size_t)DM * SEQ, (size_t)SEQ * DM);
    }
}

// round 14
// speedup vs baseline: 2.9523x; 1.0801x over previous
#include <cuda_runtime.h>
#include <cuda_fp16.h>
#include <math_constants.h>
#include <stdint.h>

#define BATCH 4
#define SEQ   2048
#define DM    1024
#define MROWS (BATCH * SEQ)

#define LO_SCALE  2048.0f
#define INV_LO    (1.0f / 2048.0f)

// ---- GEMM tiling (proven 256-thread / 8-warp config) --------------------------
#define TM 128
#define TN 128
#define BK 64                         // f16 elems per K-chunk (128 bytes/row)
#define TILE_BYTES (128 * 128)        // 16 KB per operand tile
#define STAGE_BYTES (4 * TILE_BYTES)  // Ahi,Alo,Bhi,Blo = 64 KB
#define NSTAGE 3
#define SMEM_DYN (NSTAGE * STAGE_BYTES)   // 192 KB

typedef __half h16;

// ---- scratch (static __device__: allocation-free) ------------------------------
#define AL1K __align__(1024)
__device__ AL1K h16   g_xh [MROWS * DM];
__device__ AL1K h16   g_xl [MROWS * DM];
__device__ AL1K h16   g_wAh[2 * DM * DM];   // [Wk ; Wo^T] split hi
__device__ AL1K h16   g_wAl[2 * DM * DM];
__device__ AL1K h16   g_wBh[2 * DM * DM];   // [Wq ; Wv] split hi
__device__ AL1K h16   g_wBl[2 * DM * DM];
__device__ AL1K h16   g_gh [2 * DM * DM];   // [GT ; HT] split hi
__device__ AL1K h16   g_gl [2 * DM * DM];
__device__ AL1K h16   g_qxh[(size_t)MROWS * DM];      // QG hi
__device__ AL1K h16   g_qxl[(size_t)MROWS * DM];      // QG lo
__device__ AL1K h16   g_xth[MROWS * DM];    // XH^T: [DM rows][MROWS cols] = [d][b*S+s]
__device__ AL1K float g_p  [(size_t)BATCH * SEQ * SEQ];
__device__ AL1K h16   g_ph [(size_t)BATCH * SEQ * SEQ];
__device__ AL1K h16   g_pl [(size_t)BATCH * SEQ * SEQ];
__device__ AL1K float g_w2 [DM];
__device__ AL1K float g_v  [MROWS];
__device__ AL1K float g_rb [DM];

// ---- PTX helpers -----------------------------------------------------------------
__device__ __forceinline__ uint32_t s2u(const void* p) {
    uint32_t a;
    asm("{ .reg .u64 t; cvta.to.shared.u64 t, %1; cvt.u32.u64 %0, t; }" : "=r"(a) : "l"(p));
    return a;
}
__device__ __forceinline__ void cp16(uint32_t saddr, const void* gaddr) {
    asm volatile("cp.async.cg.shared.global [%0], [%1], 16;" :: "r"(saddr), "l"(gaddr));
}
__device__ __forceinline__ void cp_commit() { asm volatile("cp.async.commit_group;"); }
__device__ __forceinline__ void cp_wait2()  { asm volatile("cp.async.wait_group 2;" ::: "memory"); }

__device__ __forceinline__ void ldm4(uint32_t* r, uint32_t addr) {
    asm volatile("ldmatrix.sync.aligned.m8n8.x4.shared.b16 {%0,%1,%2,%3}, [%4];"
                 : "=r"(r[0]), "=r"(r[1]), "=r"(r[2]), "=r"(r[3]) : "r"(addr));
}
__device__ __forceinline__ void mma_f32(float* c, const uint32_t* a, const uint32_t* b) {
    asm volatile(
        "mma.sync.aligned.m16n8k16.row.col.f32.f16.f16.f32 "
        "{%0,%1,%2,%3}, {%4,%5,%6,%7}, {%8,%9}, {%0,%1,%2,%3};"
        : "+f"(c[0]), "+f"(c[1]), "+f"(c[2]), "+f"(c[3])
        : "r"(a[0]), "r"(a[1]), "r"(a[2]), "r"(a[3]), "r"(b[0]), "r"(b[1]));
}
__device__ __forceinline__ void mma_f16(uint32_t* c, const uint32_t* a, const uint32_t* b) {
    asm volatile(
        "mma.sync.aligned.m16n8k16.row.col.f16.f16.f16.f16 "
        "{%0,%1}, {%2,%3,%4,%5}, {%6,%7}, {%0,%1};"
        : "+r"(c[0]), "+r"(c[1])
        : "r"(a[0]), "r"(a[1]), "r"(a[2]), "r"(a[3]), "r"(b[0]), "r"(b[1]));
}
__device__ __forceinline__ uint32_t pk2(float a, float b) {
    __half2 t = __floats2half2_rn(a, b);
    return *reinterpret_cast<uint32_t*>(&t);
}

// ============================================================================
// Tensor-core GEMM, 256 threads, 8 warps, warp tile 32x64 (proven config).
//   C[M,N] = scale*((Ahi+Alo/2048)[M,K] @ ((Bhi+Blo/2048)[N,K])^T)+bias
//   NTERM=3: AhBh(f32)+AhBl(f16)+AlBh(f16). NTERM=2: AhBh+AlBh. NTERM=1: AhBh.
//   OUTMODE 0: fp32 out. 1: f16 split out (lo x2048). 2: f16 hi-only out.
//   TRI: blockIdx.x encodes lower-triangle tile t -> (bm,bn); else (y,x) grid.
//   PVLIM: K truncated at causal boundary.  REVY: heavy CTAs first.
// ============================================================================
template<int OUTMODE, bool HAS_BIAS, bool TRI, bool PVLIM, bool REVY, int NTERM>
__global__ __launch_bounds__(256, 1)
void tc_gemm(const h16* __restrict__ Ah, const h16* __restrict__ Al,
             const h16* __restrict__ Bh, const h16* __restrict__ Bl,
             const float* __restrict__ bias,
             float* __restrict__ Cf, h16* __restrict__ Ch, h16* __restrict__ Cl,
             int Kfull, int ldA, int ldB, int ldC, float scale,
             size_t sA, size_t sB, size_t sC)
{
    int bm, bn;
    if (TRI) {
        const int t = blockIdx.x;
        int b_ = (int)((sqrtf(8.f * (float)t + 1.f) - 1.f) * 0.5f);
        while ((b_ + 1) * (b_ + 2) / 2 <= t) b_++;
        while (b_ * (b_ + 1) / 2 > t) b_--;
        bm = b_;
        bn = t - b_ * (b_ + 1) / 2;
    } else {
        bm = REVY ? (gridDim.y - 1 - blockIdx.y) : blockIdx.y;
        bn = blockIdx.x;
    }
    const int m0 = bm * TM;
    const int n0 = bn * TN;

    const int z = blockIdx.z;
    Ah += (size_t)z * sA;  Al += (size_t)z * sA;
    Bh += (size_t)z * sB;  Bl += (size_t)z * sB;

    extern __shared__ char dsm[];
    const uint32_t smem = s2u(dsm);

    const int tid  = threadIdx.x;
    const int wid  = tid >> 5;
    const int lane = tid & 31;
    const int wm   = wid & 3;    // 4 warp-rows  (32 M each)
    const int wn   = wid >> 2;   // 2 warp-cols  (64 N each)

    const int nchunk = PVLIM ? (m0 + TM) / BK : Kfull / BK;

    // ---- loader: each thread = half a row (4x16B segs) of each tile -----------
    const int lrow = tid >> 1;            // 0..127
    const int sb   = (tid & 1) * 4;       // seg base 0 or 4
    const char* gp[4];
    uint32_t    so[4][4];
    {
        const h16* bases[4] = {Ah, Al, Bh, Bl};
        #pragma unroll
        for (int t = 0; t < 4; t++) {
            const int off = (t < 2) ? m0 : n0;
            const int ld  = (t < 2) ? ldA : ldB;
            gp[t] = (const char*)(bases[t] + (size_t)(off + lrow) * ld);
            #pragma unroll
            for (int j = 0; j < 4; j++) {
                const int seg = sb + j;
                so[t][j] = (uint32_t)(t * TILE_BYTES + lrow * 128 +
                                      ((seg ^ (lrow & 7)) << 4));
            }
        }
    }

    auto load_stage = [&](int slot, int chunk) {
        if (chunk < nchunk) {
            const uint32_t s0 = smem + slot * STAGE_BYTES;
            const size_t goff = (size_t)chunk * 128;
            #pragma unroll
            for (int t = 0; t < 4; t++) {
                if (t == 1 && NTERM < 2) continue;   // A-lo unused
                if (t == 3 && NTERM < 3) continue;   // B-lo unused
                #pragma unroll
                for (int j = 0; j < 4; j++)
                    cp16(s0 + so[t][j], gp[t] + goff + (size_t)(sb + j) * 16);
            }
        }
        cp_commit();
    };

    float    accf[2][8][4];
    uint32_t acch[2][8][2];
    #pragma unroll
    for (int a = 0; a < 2; a++)
        #pragma unroll
        for (int b = 0; b < 8; b++) {
            #pragma unroll
            for (int c = 0; c < 4; c++) accf[a][b][c] = 0.f;
            acch[a][b][0] = 0u; acch[a][b][1] = 0u;
        }

    load_stage(0, 0);
    load_stage(1, 1);
    load_stage(2, 2);

    const int a_r  = lane & 15;
    const int a_kh = lane >> 4;
    const int b_nl = ((lane >> 4) & 1) * 8 + (lane & 7);
    const int b_kh = (lane >> 3) & 1;

    for (int i = 0; i < nchunk; i++) {
        cp_wait2();
        __syncthreads();
        const uint32_t s0 = smem + (i % 3) * STAGE_BYTES;

        #pragma unroll
        for (int kk = 0; kk < 4; kk++) {
            uint32_t ahf[2][4], alf[2][4], bhf[4][4], blf[4][4];
            #pragma unroll
            for (int mt = 0; mt < 2; mt++) {
                const int row = wm * 32 + mt * 16 + a_r;
                const int seg = kk * 2 + a_kh;
                const uint32_t off = (uint32_t)(row * 128 + ((seg ^ (row & 7)) << 4));
                ldm4(ahf[mt], s0 + 0 * TILE_BYTES + off);
                if (NTERM >= 2) ldm4(alf[mt], s0 + 1 * TILE_BYTES + off);
            }
            #pragma unroll
            for (int p = 0; p < 4; p++) {
                const int row = wn * 64 + p * 16 + b_nl;
                const int seg = kk * 2 + b_kh;
                const uint32_t off = (uint32_t)(row * 128 + ((seg ^ (row & 7)) << 4));
                ldm4(bhf[p], s0 + 2 * TILE_BYTES + off);
                if (NTERM >= 3) ldm4(blf[p], s0 + 3 * TILE_BYTES + off);
            }
            #pragma unroll
            for (int mt = 0; mt < 2; mt++)
                #pragma unroll
                for (int nt = 0; nt < 8; nt++)
                    mma_f32(accf[mt][nt], ahf[mt], &bhf[nt >> 1][(nt & 1) * 2]);
            if (NTERM >= 3) {
                #pragma unroll
                for (int mt = 0; mt < 2; mt++)
                    #pragma unroll
                    for (int nt = 0; nt < 8; nt++)
                        mma_f16(acch[mt][nt], ahf[mt], &blf[nt >> 1][(nt & 1) * 2]);
            }
            if (NTERM >= 2) {
                #pragma unroll
                for (int mt = 0; mt < 2; mt++)
                    #pragma unroll
                    for (int nt = 0; nt < 8; nt++)
                        mma_f16(acch[mt][nt], alf[mt], &bhf[nt >> 1][(nt & 1) * 2]);
            }
        }
        __syncthreads();
        load_stage(i % 3, i + 3);
    }

    #pragma unroll
    for (int mt = 0; mt < 2; mt++) {
        #pragma unroll
        for (int h = 0; h < 2; h++) {
            const int row = m0 + wm * 32 + mt * 16 + (lane >> 2) + 8 * h;
            #pragma unroll
            for (int nt = 0; nt < 8; nt++) {
                const int col = n0 + wn * 64 + nt * 8 + (lane & 3) * 2;
                float c0 = 0.f, c1 = 0.f;
                if (NTERM >= 2) {
                    const __half2 hc = *reinterpret_cast<const __half2*>(&acch[mt][nt][h]);
                    c0 = __low2float(hc)  * INV_LO;
                    c1 = __high2float(hc) * INV_LO;
                }
                float v0 = (accf[mt][nt][2 * h + 0] + c0) * scale;
                float v1 = (accf[mt][nt][2 * h + 1] + c1) * scale;
                if (HAS_BIAS) {
                    const float2 bb = *reinterpret_cast<const float2*>(bias + col);
                    v0 += bb.x; v1 += bb.y;
                }
                if (OUTMODE == 0) {
                    *reinterpret_cast<float2*>(
                        Cf + (size_t)z * sC + (size_t)row * ldC + col) =
                        make_float2(v0, v1);
                } else if (OUTMODE == 1) {
                    float h0 = __half2float(__float2half_rn(v0));
                    float h1 = __half2float(__float2half_rn(v1));
                    *reinterpret_cast<uint32_t*>(
                        Ch + (size_t)z * sC + (size_t)row * ldC + col) = pk2(h0, h1);
                    *reinterpret_cast<uint32_t*>(
                        Cl + (size_t)z * sC + (size_t)row * ldC + col) =
                        pk2((v0 - h0) * LO_SCALE, (v1 - h1) * LO_SCALE);
                } else {
                    *reinterpret_cast<uint32_t*>(
                        Ch + (size_t)z * sC + (size_t)row * ldC + col) = pk2(v0, v1);
                }
            }
        }
    }
}

// ============================================================================
// prep kernels (all lo outputs pre-scaled x2048)
// ============================================================================
__global__ void split_kernel(const float* __restrict__ in,
                             h16* __restrict__ oh, h16* __restrict__ ol, int n)
{
    int i = blockIdx.x * blockDim.x + threadIdx.x;
    if (i >= n) return;
    float v = in[i];
    h16 h = __float2half_rn(v);
    oh[i] = h;
    ol[i] = __float2half_rn((v - __half2float(h)) * LO_SCALE);
}

__global__ void tsplit_kernel(const float* __restrict__ in,
                              h16* __restrict__ oh, h16* __restrict__ ol,
                              int R, int C)
{
    __shared__ float t[32][33];
    const int c0 = blockIdx.x * 32, r0 = blockIdx.y * 32;
    const int tx = threadIdx.x, ty = threadIdx.y;
    #pragma unroll
    for (int k = 0; k < 4; k++)
        t[ty + 8 * k][tx] = in[(size_t)(r0 + ty + 8 * k) * C + c0 + tx];
    __syncthreads();
    #pragma unroll
    for (int k = 0; k < 4; k++) {
        float v = t[tx][ty + 8 * k];
        h16 h = __float2half_rn(v);
        size_t o = (size_t)(c0 + ty + 8 * k) * R + r0 + tx;
        oh[o] = h;
        ol[o] = __float2half_rn((v - __half2float(h)) * LO_SCALE);
    }
}

__global__ void wkbq_kernel(const float* __restrict__ Wk, const float* __restrict__ bq,
                            float* __restrict__ w2)
{
    int w = (blockIdx.x * blockDim.x + threadIdx.x) >> 5;
    int lane = threadIdx.x & 31;
    if (w >= DM) return;
    float s = 0.f;
    for (int e = lane; e < DM; e += 32) s += Wk[(size_t)w * DM + e] * bq[e];
    #pragma unroll
    for (int o = 16; o > 0; o >>= 1) s += __shfl_down_sync(0xffffffffu, s, o);
    if (lane == 0) w2[w] = s;
}

// rb[d] = sum_e bv[e]*Wo[e,d] + bo[d]; 32 blocks x (8 e-slices x 32 d), coalesced.
__global__ void rb_kernel(const float* __restrict__ Wo, const float* __restrict__ bv,
                          const float* __restrict__ bo, float* __restrict__ rb)
{
    __shared__ float red[8][32];
    const int tx = threadIdx.x & 31;
    const int ty = threadIdx.x >> 5;
    const int d = blockIdx.x * 32 + tx;
    float s = 0.f;
    for (int e = ty; e < DM; e += 8)
        s += bv[e] * Wo[(size_t)e * DM + d];
    red[ty][tx] = s;
    __syncthreads();
    if (ty == 0) {
        float t = 0.f;
        #pragma unroll
        for (int j = 0; j < 8; j++) t += red[j][tx];
        rb[d] = t + bo[d];
    }
}

__global__ void vvec_kernel(const float* __restrict__ x, const float* __restrict__ w2,
                            float* __restrict__ v)
{
    int w = (blockIdx.x * blockDim.x + threadIdx.x) >> 5;
    int lane = threadIdx.x & 31;
    if (w >= MROWS) return;
    float s = 0.f;
    for (int d = lane; d < DM; d += 32) s += x[(size_t)w * DM + d] * w2[d];
    #pragma unroll
    for (int o = 16; o > 0; o >>= 1) s += __shfl_down_sync(0xffffffffu, s, o);
    if (lane == 0) v[w] = s;
}

// causal softmax, row cached in smem (single global read of p).
__global__ __launch_bounds__(256)
void softmax_split_kernel(const float* __restrict__ P, const float* __restrict__ V,
                          h16* __restrict__ Ph, h16* __restrict__ Pl)
{
    __shared__ float row[SEQ];
    __shared__ float red[256];

    const int rowi = blockIdx.x;
    const int b = rowi / SEQ, q = rowi % SEQ;
    const size_t off = (size_t)b * SEQ * SEQ + (size_t)q * SEQ;
    const float* p = P + off;
    const float* vv = V + (size_t)b * SEQ;
    h16* ph = Ph + off;
    h16* pl = Pl + off;
    const int n = q + 1;
    const int tid = threadIdx.x;

    float mx = -CUDART_INF_F;
    for (int k = tid; k < n; k += 256) {
        float l = p[k] + 0.125f * vv[k];
        row[k] = l;
        mx = fmaxf(mx, l);
    }
    red[tid] = mx; __syncthreads();
    #pragma unroll
    for (int s = 128; s > 0; s >>= 1) {
        if (tid < s) red[tid] = fmaxf(red[tid], red[tid + s]);
        __syncthreads();
    }
    mx = red[0]; __syncthreads();

    float sum = 0.f;
    for (int k = tid; k < n; k += 256) {
        float e = expf(row[k] - mx);
        row[k] = e;
        sum += e;
    }
    red[tid] = sum; __syncthreads();
    #pragma unroll
    for (int s = 128; s > 0; s >>= 1) {
        if (tid < s) red[tid] += red[tid + s];
        __syncthreads();
    }
    const float inv = 1.f / red[0];
    __syncthreads();

    for (int k = tid; k < n; k += 256) {
        float w = row[k] * inv;
        h16 h = __float2half_rn(w);
        ph[k] = h;
        pl[k] = __float2half_rn((w - __half2float(h)) * LO_SCALE);
    }
    const int fillEnd = ((q >> 7) + 1) << 7;
    for (int k = n + tid; k < fillEnd; k += 256) {
        ph[k] = __float2half_rn(0.f);
        pl[k] = __float2half_rn(0.f);
    }
}

// ============================================================================
extern "C" void kernel_launch(void* const* d_in, const int*, int, void* d_out, int)
{
    const float* x  = (const float*)d_in[0];
    const float* Wq = (const float*)d_in[1];
    const float* bq = (const float*)d_in[2];
    const float* Wk = (const float*)d_in[3];
    const float* bk = (const float*)d_in[4];   (void)bk;  // cancels in softmax
    const float* Wv = (const float*)d_in[5];
    const float* bv = (const float*)d_in[6];
    const float* Wo = (const float*)d_in[7];
    const float* bo = (const float*)d_in[8];
    float* out = (float*)d_out;

    h16 *xh, *xl, *wAh, *wAl, *wBh, *wBl, *gh, *gl, *qxh, *qxl, *xth, *phh, *pll;
    float *p, *w2, *v, *rb;
    cudaGetSymbolAddress((void**)&xh,  g_xh);  cudaGetSymbolAddress((void**)&xl,  g_xl);
    cudaGetSymbolAddress((void**)&wAh, g_wAh); cudaGetSymbolAddress((void**)&wAl, g_wAl);
    cudaGetSymbolAddress((void**)&wBh, g_wBh); cudaGetSymbolAddress((void**)&wBl, g_wBl);
    cudaGetSymbolAddress((void**)&gh,  g_gh);  cudaGetSymbolAddress((void**)&gl,  g_gl);
    cudaGetSymbolAddress((void**)&qxh, g_qxh); cudaGetSymbolAddress((void**)&qxl, g_qxl);
    cudaGetSymbolAddress((void**)&xth, g_xth);
    cudaGetSymbolAddress((void**)&p,   g_p);
    cudaGetSymbolAddress((void**)&phh, g_ph);  cudaGetSymbolAddress((void**)&pll, g_pl);
    cudaGetSymbolAddress((void**)&w2,  g_w2);  cudaGetSymbolAddress((void**)&v,   g_v);
    cudaGetSymbolAddress((void**)&rb,  g_rb);

    cudaFuncSetAttribute(tc_gemm<1, false, false, false, false, 3>, cudaFuncAttributeMaxDynamicSharedMemorySize, SMEM_DYN);
    cudaFuncSetAttribute(tc_gemm<1, false, false, false, false, 2>, cudaFuncAttributeMaxDynamicSharedMemorySize, SMEM_DYN);
    cudaFuncSetAttribute(tc_gemm<2, false, false, false, false, 1>, cudaFuncAttributeMaxDynamicSharedMemorySize, SMEM_DYN);
    cudaFuncSetAttribute(tc_gemm<0, false, true,  false, false, 2>, cudaFuncAttributeMaxDynamicSharedMemorySize, SMEM_DYN);
    cudaFuncSetAttribute(tc_gemm<0, true,  false, true,  true,  2>, cudaFuncAttributeMaxDynamicSharedMemorySize, SMEM_DYN);

    // ---- prep: splits + bias vectors ---------------------------------------
    split_kernel<<<(MROWS * DM + 255) / 256, 256>>>(x, xh, xl, MROWS * DM);
    split_kernel<<<(DM * DM + 255) / 256, 256>>>(Wk, wAh,           wAl,           DM * DM);
    split_kernel<<<(DM * DM + 255) / 256, 256>>>(Wq, wBh,           wBl,           DM * DM);
    split_kernel<<<(DM * DM + 255) / 256, 256>>>(Wv, wBh + DM * DM, wBl + DM * DM, DM * DM);
    {
        dim3 blk(32, 8), grid(DM / 32, DM / 32);
        tsplit_kernel<<<grid, blk>>>(Wo, wAh + DM * DM, wAl + DM * DM, DM, DM);
    }
    wkbq_kernel<<<DM * 32 / 256, 256>>>(Wk, bq, w2);
    rb_kernel<<<DM / 32, 256>>>(Wo, bv, bo, rb);
    vvec_kernel<<<MROWS * 32 / 256, 256>>>(x, w2, v);

    // ---- GT = Wk*Wq^T ; HT = Wo^T*Wv^T-form (z=2, FULL 3-term) ----------------
    {
        dim3 grid(DM / TN, DM / TM, 2), blk(256);
        tc_gemm<1, false, false, false, false, 3><<<grid, blk, SMEM_DYN>>>(
            wAh, wAl, wBh, wBl, nullptr, nullptr, gh, gl,
            DM, DM, DM, DM, 1.f,
            (size_t)DM * DM, (size_t)DM * DM, (size_t)DM * DM);
    }

    // ---- QG = x*GT (2-term: logit path needs precision) ------------------------
    {
        dim3 grid(DM / TN, MROWS / TM, 1), blk(256);
        tc_gemm<1, false, false, false, false, 2><<<grid, blk, SMEM_DYN>>>(
            xh, xl, gh, gl, nullptr, nullptr, qxh, qxl,
            DM, DM, DM, DM, 1.f, 0, 0, 0);
    }

    // ---- XHT[d][s] = HT(d,:) . x(s,:)  (1-term, f16 hi out, ldC = MROWS) --------
    // Direct transposed result: replaces XH GEMM + txsplit.
    {
        dim3 grid(MROWS / TN, DM / TM, 1), blk(256);
        tc_gemm<2, false, false, false, false, 1><<<grid, blk, SMEM_DYN>>>(
            gh + (size_t)DM * DM, gl + (size_t)DM * DM, xh, xl,
            nullptr, nullptr, xth, nullptr,
            DM, DM, DM, MROWS, 1.f, 0, 0, 0);
    }

    // ---- scores core = 0.125 * QG @ x^T (compact triangular grid, 2-term) ------
    {
        dim3 grid(136, 1, BATCH), blk(256);
        tc_gemm<0, false, true, false, false, 2><<<grid, blk, SMEM_DYN>>>(
            qxh, qxl, xh, xl, nullptr, p, nullptr, nullptr,
            DM, DM, DM, SEQ, 0.125f,
            (size_t)SEQ * DM, (size_t)SEQ * DM, (size_t)SEQ * SEQ);
    }

    // ---- softmax over (scores + 0.125*v[j]) -> split f16 weights ----------------
    softmax_split_kernel<<<MROWS, 256>>>(p, v, phh, pll);

    // ---- out = P @ XHT^T + (bv*Wo + bo)  (2-term; B rows are XHT rows, ld=MROWS)
    {
        dim3 grid(DM / TN, SEQ / TM, BATCH), blk(256);
        tc_gemm<0, true, false, true, true, 2><<<grid, blk, SMEM_DYN>>>(
            phh, pll, xth, nullptr, rb, out, nullptr, nullptr,
            SEQ, SEQ, MROWS, DM, 1.f,
            (size_t)SEQ * SEQ, (size_t)SEQ, (size_t)SEQ * DM);
    }
}

// round 15
// speedup vs baseline: 3.5563x; 1.2046x over previous
#include <cuda_runtime.h>
#include <cuda_fp16.h>
#include <math_constants.h>
#include <stdint.h>

#define BATCH 4
#define SEQ   2048
#define DM    1024
#define MROWS (BATCH * SEQ)

#define LO_SCALE  2048.0f
#define INV_LO    (1.0f / 2048.0f)

// ---- GEMM tiling (proven 256-thread / 8-warp config) --------------------------
#define TM 128
#define TN 128
#define BK 64                         // f16 elems per K-chunk (128 bytes/row)
#define TILE_BYTES (128 * 128)        // 16 KB per operand tile
#define STAGE_BYTES (4 * TILE_BYTES)  // Ahi,Alo,Bhi,Blo = 64 KB
#define NSTAGE 3
#define SMEM_DYN (NSTAGE * STAGE_BYTES)   // 192 KB

typedef __half h16;

// ---- scratch (static __device__: allocation-free) ------------------------------
#define AL1K __align__(1024)
__device__ AL1K h16   g_xh [MROWS * DM];
__device__ AL1K h16   g_xl [MROWS * DM];
__device__ AL1K h16   g_wAh[2 * DM * DM];   // [Wk ; Wo^T] split hi
__device__ AL1K h16   g_wAl[2 * DM * DM];
__device__ AL1K h16   g_wBh[2 * DM * DM];   // [Wq ; Wv] split hi
__device__ AL1K h16   g_wBl[2 * DM * DM];
__device__ AL1K h16   g_gh [2 * DM * DM];   // [GT ; HT] split hi
__device__ AL1K h16   g_gl [2 * DM * DM];
__device__ AL1K h16   g_qgh[(size_t)MROWS * DM];      // QG hi (lo has no consumer)
__device__ AL1K h16   g_xth[MROWS * DM];    // XH^T: [DM rows][MROWS cols]
__device__ AL1K float g_p  [(size_t)BATCH * SEQ * SEQ];
__device__ AL1K h16   g_ph [(size_t)BATCH * SEQ * SEQ];
__device__ AL1K float g_w2 [DM];
__device__ AL1K float g_v  [MROWS];
__device__ AL1K float g_rb [DM];

// ---- PTX helpers -----------------------------------------------------------------
__device__ __forceinline__ uint32_t s2u(const void* p) {
    uint32_t a;
    asm("{ .reg .u64 t; cvta.to.shared.u64 t, %1; cvt.u32.u64 %0, t; }" : "=r"(a) : "l"(p));
    return a;
}
__device__ __forceinline__ void cp16(uint32_t saddr, const void* gaddr) {
    asm volatile("cp.async.cg.shared.global [%0], [%1], 16;" :: "r"(saddr), "l"(gaddr));
}
__device__ __forceinline__ void cp_commit() { asm volatile("cp.async.commit_group;"); }
__device__ __forceinline__ void cp_wait2()  { asm volatile("cp.async.wait_group 2;" ::: "memory"); }

__device__ __forceinline__ void ldm4(uint32_t* r, uint32_t addr) {
    asm volatile("ldmatrix.sync.aligned.m8n8.x4.shared.b16 {%0,%1,%2,%3}, [%4];"
                 : "=r"(r[0]), "=r"(r[1]), "=r"(r[2]), "=r"(r[3]) : "r"(addr));
}
__device__ __forceinline__ void mma_f32(float* c, const uint32_t* a, const uint32_t* b) {
    asm volatile(
        "mma.sync.aligned.m16n8k16.row.col.f32.f16.f16.f32 "
        "{%0,%1,%2,%3}, {%4,%5,%6,%7}, {%8,%9}, {%0,%1,%2,%3};"
        : "+f"(c[0]), "+f"(c[1]), "+f"(c[2]), "+f"(c[3])
        : "r"(a[0]), "r"(a[1]), "r"(a[2]), "r"(a[3]), "r"(b[0]), "r"(b[1]));
}
__device__ __forceinline__ void mma_f16(uint32_t* c, const uint32_t* a, const uint32_t* b) {
    asm volatile(
        "mma.sync.aligned.m16n8k16.row.col.f16.f16.f16.f16 "
        "{%0,%1}, {%2,%3,%4,%5}, {%6,%7}, {%0,%1};"
        : "+r"(c[0]), "+r"(c[1])
        : "r"(a[0]), "r"(a[1]), "r"(a[2]), "r"(a[3]), "r"(b[0]), "r"(b[1]));
}
__device__ __forceinline__ uint32_t pk2(float a, float b) {
    __half2 t = __floats2half2_rn(a, b);
    return *reinterpret_cast<uint32_t*>(&t);
}

// ============================================================================
// Tensor-core GEMM, 256 threads, 8 warps, warp tile 32x64 (proven config).
//   C[M,N] = scale*((Ahi+Alo/2048)[M,K] @ ((Bhi+Blo/2048)[N,K])^T)+bias
//   NTERM=3: AhBh(f32)+AhBl(f16)+AlBh(f16). NTERM=2: AhBh+AlBh. NTERM=1: AhBh.
//   OUTMODE 0: fp32 out. 1: f16 split out (lo x2048). 2: f16 hi-only out.
//   TRI: blockIdx.x encodes lower-triangle tile t -> (bm,bn); else (y,x) grid.
//   PVLIM: K truncated at causal boundary.  REVY: heavy CTAs first.
// ============================================================================
template<int OUTMODE, bool HAS_BIAS, bool TRI, bool PVLIM, bool REVY, int NTERM>
__global__ __launch_bounds__(256, 1)
void tc_gemm(const h16* __restrict__ Ah, const h16* __restrict__ Al,
             const h16* __restrict__ Bh, const h16* __restrict__ Bl,
             const float* __restrict__ bias,
             float* __restrict__ Cf, h16* __restrict__ Ch, h16* __restrict__ Cl,
             int Kfull, int ldA, int ldB, int ldC, float scale,
             size_t sA, size_t sB, size_t sC)
{
    int bm, bn;
    if (TRI) {
        const int t = blockIdx.x;
        int b_ = (int)((sqrtf(8.f * (float)t + 1.f) - 1.f) * 0.5f);
        while ((b_ + 1) * (b_ + 2) / 2 <= t) b_++;
        while (b_ * (b_ + 1) / 2 > t) b_--;
        bm = b_;
        bn = t - b_ * (b_ + 1) / 2;
    } else {
        bm = REVY ? (gridDim.y - 1 - blockIdx.y) : blockIdx.y;
        bn = blockIdx.x;
    }
    const int m0 = bm * TM;
    const int n0 = bn * TN;

    const int z = blockIdx.z;
    Ah += (size_t)z * sA;  if (NTERM >= 2) Al += (size_t)z * sA;
    Bh += (size_t)z * sB;  if (NTERM >= 3) Bl += (size_t)z * sB;

    extern __shared__ char dsm[];
    const uint32_t smem = s2u(dsm);

    const int tid  = threadIdx.x;
    const int wid  = tid >> 5;
    const int lane = tid & 31;
    const int wm   = wid & 3;    // 4 warp-rows  (32 M each)
    const int wn   = wid >> 2;   // 2 warp-cols  (64 N each)

    const int nchunk = PVLIM ? (m0 + TM) / BK : Kfull / BK;

    // ---- loader: each thread = half a row (4x16B segs) of each tile -----------
    const int lrow = tid >> 1;            // 0..127
    const int sb   = (tid & 1) * 4;       // seg base 0 or 4
    const char* gp[4];
    uint32_t    so[4][4];
    {
        const h16* bases[4] = {Ah, Al, Bh, Bl};
        #pragma unroll
        for (int t = 0; t < 4; t++) {
            if ((t == 1 && NTERM < 2) || (t == 3 && NTERM < 3)) { gp[t] = nullptr; continue; }
            const int off = (t < 2) ? m0 : n0;
            const int ld  = (t < 2) ? ldA : ldB;
            gp[t] = (const char*)(bases[t] + (size_t)(off + lrow) * ld);
            #pragma unroll
            for (int j = 0; j < 4; j++) {
                const int seg = sb + j;
                so[t][j] = (uint32_t)(t * TILE_BYTES + lrow * 128 +
                                      ((seg ^ (lrow & 7)) << 4));
            }
        }
    }

    auto load_stage = [&](int slot, int chunk) {
        if (chunk < nchunk) {
            const uint32_t s0 = smem + slot * STAGE_BYTES;
            const size_t goff = (size_t)chunk * 128;
            #pragma unroll
            for (int t = 0; t < 4; t++) {
                if (t == 1 && NTERM < 2) continue;   // A-lo unused
                if (t == 3 && NTERM < 3) continue;   // B-lo unused
                #pragma unroll
                for (int j = 0; j < 4; j++)
                    cp16(s0 + so[t][j], gp[t] + goff + (size_t)(sb + j) * 16);
            }
        }
        cp_commit();
    };

    float    accf[2][8][4];
    uint32_t acch[2][8][2];
    #pragma unroll
    for (int a = 0; a < 2; a++)
        #pragma unroll
        for (int b = 0; b < 8; b++) {
            #pragma unroll
            for (int c = 0; c < 4; c++) accf[a][b][c] = 0.f;
            acch[a][b][0] = 0u; acch[a][b][1] = 0u;
        }

    load_stage(0, 0);
    load_stage(1, 1);
    load_stage(2, 2);

    const int a_r  = lane & 15;
    const int a_kh = lane >> 4;
    const int b_nl = ((lane >> 4) & 1) * 8 + (lane & 7);
    const int b_kh = (lane >> 3) & 1;

    for (int i = 0; i < nchunk; i++) {
        cp_wait2();
        __syncthreads();
        const uint32_t s0 = smem + (i % 3) * STAGE_BYTES;

        #pragma unroll
        for (int kk = 0; kk < 4; kk++) {
            uint32_t ahf[2][4], alf[2][4], bhf[4][4], blf[4][4];
            #pragma unroll
            for (int mt = 0; mt < 2; mt++) {
                const int row = wm * 32 + mt * 16 + a_r;
                const int seg = kk * 2 + a_kh;
                const uint32_t off = (uint32_t)(row * 128 + ((seg ^ (row & 7)) << 4));
                ldm4(ahf[mt], s0 + 0 * TILE_BYTES + off);
                if (NTERM >= 2) ldm4(alf[mt], s0 + 1 * TILE_BYTES + off);
            }
            #pragma unroll
            for (int p = 0; p < 4; p++) {
                const int row = wn * 64 + p * 16 + b_nl;
                const int seg = kk * 2 + b_kh;
                const uint32_t off = (uint32_t)(row * 128 + ((seg ^ (row & 7)) << 4));
                ldm4(bhf[p], s0 + 2 * TILE_BYTES + off);
                if (NTERM >= 3) ldm4(blf[p], s0 + 3 * TILE_BYTES + off);
            }
            #pragma unroll
            for (int mt = 0; mt < 2; mt++)
                #pragma unroll
                for (int nt = 0; nt < 8; nt++)
                    mma_f32(accf[mt][nt], ahf[mt], &bhf[nt >> 1][(nt & 1) * 2]);
            if (NTERM >= 3) {
                #pragma unroll
                for (int mt = 0; mt < 2; mt++)
                    #pragma unroll
                    for (int nt = 0; nt < 8; nt++)
                        mma_f16(acch[mt][nt], ahf[mt], &blf[nt >> 1][(nt & 1) * 2]);
            }
            if (NTERM >= 2) {
                #pragma unroll
                for (int mt = 0; mt < 2; mt++)
                    #pragma unroll
                    for (int nt = 0; nt < 8; nt++)
                        mma_f16(acch[mt][nt], alf[mt], &bhf[nt >> 1][(nt & 1) * 2]);
            }
        }
        __syncthreads();
        load_stage(i % 3, i + 3);
    }

    #pragma unroll
    for (int mt = 0; mt < 2; mt++) {
        #pragma unroll
        for (int h = 0; h < 2; h++) {
            const int row = m0 + wm * 32 + mt * 16 + (lane >> 2) + 8 * h;
            #pragma unroll
            for (int nt = 0; nt < 8; nt++) {
                const int col = n0 + wn * 64 + nt * 8 + (lane & 3) * 2;
                float c0 = 0.f, c1 = 0.f;
                if (NTERM >= 2) {
                    const __half2 hc = *reinterpret_cast<const __half2*>(&acch[mt][nt][h]);
                    c0 = __low2float(hc)  * INV_LO;
                    c1 = __high2float(hc) * INV_LO;
                }
                float v0 = (accf[mt][nt][2 * h + 0] + c0) * scale;
                float v1 = (accf[mt][nt][2 * h + 1] + c1) * scale;
                if (HAS_BIAS) {
                    const float2 bb = *reinterpret_cast<const float2*>(bias + col);
                    v0 += bb.x; v1 += bb.y;
                }
                if (OUTMODE == 0) {
                    *reinterpret_cast<float2*>(
                        Cf + (size_t)z * sC + (size_t)row * ldC + col) =
                        make_float2(v0, v1);
                } else if (OUTMODE == 1) {
                    float h0 = __half2float(__float2half_rn(v0));
                    float h1 = __half2float(__float2half_rn(v1));
                    *reinterpret_cast<uint32_t*>(
                        Ch + (size_t)z * sC + (size_t)row * ldC + col) = pk2(h0, h1);
                    *reinterpret_cast<uint32_t*>(
                        Cl + (size_t)z * sC + (size_t)row * ldC + col) =
                        pk2((v0 - h0) * LO_SCALE, (v1 - h1) * LO_SCALE);
                } else {
                    *reinterpret_cast<uint32_t*>(
                        Ch + (size_t)z * sC + (size_t)row * ldC + col) = pk2(v0, v1);
                }
            }
        }
    }
}

// ============================================================================
// prep kernels (all lo outputs pre-scaled x2048)
// ============================================================================
__global__ void split_kernel(const float* __restrict__ in,
                             h16* __restrict__ oh, h16* __restrict__ ol, int n)
{
    int i = blockIdx.x * blockDim.x + threadIdx.x;
    if (i >= n) return;
    float v = in[i];
    h16 h = __float2half_rn(v);
    oh[i] = h;
    ol[i] = __float2half_rn((v - __half2float(h)) * LO_SCALE);
}

__global__ void tsplit_kernel(const float* __restrict__ in,
                              h16* __restrict__ oh, h16* __restrict__ ol,
                              int R, int C)
{
    __shared__ float t[32][33];
    const int c0 = blockIdx.x * 32, r0 = blockIdx.y * 32;
    const int tx = threadIdx.x, ty = threadIdx.y;
    #pragma unroll
    for (int k = 0; k < 4; k++)
        t[ty + 8 * k][tx] = in[(size_t)(r0 + ty + 8 * k) * C + c0 + tx];
    __syncthreads();
    #pragma unroll
    for (int k = 0; k < 4; k++) {
        float v = t[tx][ty + 8 * k];
        h16 h = __float2half_rn(v);
        size_t o = (size_t)(c0 + ty + 8 * k) * R + r0 + tx;
        oh[o] = h;
        ol[o] = __float2half_rn((v - __half2float(h)) * LO_SCALE);
    }
}

__global__ void wkbq_kernel(const float* __restrict__ Wk, const float* __restrict__ bq,
                            float* __restrict__ w2)
{
    int w = (blockIdx.x * blockDim.x + threadIdx.x) >> 5;
    int lane = threadIdx.x & 31;
    if (w >= DM) return;
    float s = 0.f;
    for (int e = lane; e < DM; e += 32) s += Wk[(size_t)w * DM + e] * bq[e];
    #pragma unroll
    for (int o = 16; o > 0; o >>= 1) s += __shfl_down_sync(0xffffffffu, s, o);
    if (lane == 0) w2[w] = s;
}

__global__ void rb_kernel(const float* __restrict__ Wo, const float* __restrict__ bv,
                          const float* __restrict__ bo, float* __restrict__ rb)
{
    __shared__ float red[8][32];
    const int tx = threadIdx.x & 31;
    const int ty = threadIdx.x >> 5;
    const int d = blockIdx.x * 32 + tx;
    float s = 0.f;
    for (int e = ty; e < DM; e += 8)
        s += bv[e] * Wo[(size_t)e * DM + d];
    red[ty][tx] = s;
    __syncthreads();
    if (ty == 0) {
        float t = 0.f;
        #pragma unroll
        for (int j = 0; j < 8; j++) t += red[j][tx];
        rb[d] = t + bo[d];
    }
}

__global__ void vvec_kernel(const float* __restrict__ x, const float* __restrict__ w2,
                            float* __restrict__ v)
{
    int w = (blockIdx.x * blockDim.x + threadIdx.x) >> 5;
    int lane = threadIdx.x & 31;
    if (w >= MROWS) return;
    float s = 0.f;
    for (int d = lane; d < DM; d += 32) s += x[(size_t)w * DM + d] * w2[d];
    #pragma unroll
    for (int o = 16; o > 0; o >>= 1) s += __shfl_down_sync(0xffffffffu, s, o);
    if (lane == 0) v[w] = s;
}

// causal softmax, row cached in smem; writes f16 hi weights only.
__global__ __launch_bounds__(256)
void softmax_kernel(const float* __restrict__ P, const float* __restrict__ V,
                    h16* __restrict__ Ph)
{
    __shared__ float row[SEQ];
    __shared__ float red[256];

    const int rowi = blockIdx.x;
    const int b = rowi / SEQ, q = rowi % SEQ;
    const size_t off = (size_t)b * SEQ * SEQ + (size_t)q * SEQ;
    const float* p = P + off;
    const float* vv = V + (size_t)b * SEQ;
    h16* ph = Ph + off;
    const int n = q + 1;
    const int tid = threadIdx.x;

    float mx = -CUDART_INF_F;
    for (int k = tid; k < n; k += 256) {
        float l = p[k] + 0.125f * vv[k];
        row[k] = l;
        mx = fmaxf(mx, l);
    }
    red[tid] = mx; __syncthreads();
    #pragma unroll
    for (int s = 128; s > 0; s >>= 1) {
        if (tid < s) red[tid] = fmaxf(red[tid], red[tid + s]);
        __syncthreads();
    }
    mx = red[0]; __syncthreads();

    float sum = 0.f;
    for (int k = tid; k < n; k += 256) {
        float e = expf(row[k] - mx);
        row[k] = e;
        sum += e;
    }
    red[tid] = sum; __syncthreads();
    #pragma unroll
    for (int s = 128; s > 0; s >>= 1) {
        if (tid < s) red[tid] += red[tid + s];
        __syncthreads();
    }
    const float inv = 1.f / red[0];
    __syncthreads();

    for (int k = tid; k < n; k += 256) {
        ph[k] = __float2half_rn(row[k] * inv);
    }
    const int fillEnd = ((q >> 7) + 1) << 7;
    for (int k = n + tid; k < fillEnd; k += 256) {
        ph[k] = __float2half_rn(0.f);
    }
}

// ============================================================================
extern "C" void kernel_launch(void* const* d_in, const int*, int, void* d_out, int)
{
    const float* x  = (const float*)d_in[0];
    const float* Wq = (const float*)d_in[1];
    const float* bq = (const float*)d_in[2];
    const float* Wk = (const float*)d_in[3];
    const float* bk = (const float*)d_in[4];   (void)bk;  // cancels in softmax
    const float* Wv = (const float*)d_in[5];
    const float* bv = (const float*)d_in[6];
    const float* Wo = (const float*)d_in[7];
    const float* bo = (const float*)d_in[8];
    float* out = (float*)d_out;

    h16 *xh, *xl, *wAh, *wAl, *wBh, *wBl, *gh, *gl, *qgh, *xth, *phh;
    float *p, *w2, *v, *rb;
    cudaGetSymbolAddress((void**)&xh,  g_xh);  cudaGetSymbolAddress((void**)&xl,  g_xl);
    cudaGetSymbolAddress((void**)&wAh, g_wAh); cudaGetSymbolAddress((void**)&wAl, g_wAl);
    cudaGetSymbolAddress((void**)&wBh, g_wBh); cudaGetSymbolAddress((void**)&wBl, g_wBl);
    cudaGetSymbolAddress((void**)&gh,  g_gh);  cudaGetSymbolAddress((void**)&gl,  g_gl);
    cudaGetSymbolAddress((void**)&qgh, g_qgh);
    cudaGetSymbolAddress((void**)&xth, g_xth);
    cudaGetSymbolAddress((void**)&p,   g_p);
    cudaGetSymbolAddress((void**)&phh, g_ph);
    cudaGetSymbolAddress((void**)&w2,  g_w2);  cudaGetSymbolAddress((void**)&v,   g_v);
    cudaGetSymbolAddress((void**)&rb,  g_rb);

    cudaFuncSetAttribute(tc_gemm<1, false, false, false, false, 3>, cudaFuncAttributeMaxDynamicSharedMemorySize, SMEM_DYN);
    cudaFuncSetAttribute(tc_gemm<2, false, false, false, false, 2>, cudaFuncAttributeMaxDynamicSharedMemorySize, SMEM_DYN);
    cudaFuncSetAttribute(tc_gemm<2, false, false, false, false, 1>, cudaFuncAttributeMaxDynamicSharedMemorySize, SMEM_DYN);
    cudaFuncSetAttribute(tc_gemm<0, false, true,  false, false, 1>, cudaFuncAttributeMaxDynamicSharedMemorySize, SMEM_DYN);
    cudaFuncSetAttribute(tc_gemm<0, true,  false, true,  true,  1>, cudaFuncAttributeMaxDynamicSharedMemorySize, SMEM_DYN);

    // ---- prep: splits + bias vectors ---------------------------------------
    split_kernel<<<(MROWS * DM + 255) / 256, 256>>>(x, xh, xl, MROWS * DM);
    split_kernel<<<(DM * DM + 255) / 256, 256>>>(Wk, wAh,           wAl,           DM * DM);
    split_kernel<<<(DM * DM + 255) / 256, 256>>>(Wq, wBh,           wBl,           DM * DM);
    split_kernel<<<(DM * DM + 255) / 256, 256>>>(Wv, wBh + DM * DM, wBl + DM * DM, DM * DM);
    {
        dim3 blk(32, 8), grid(DM / 32, DM / 32);
        tsplit_kernel<<<grid, blk>>>(Wo, wAh + DM * DM, wAl + DM * DM, DM, DM);
    }
    wkbq_kernel<<<DM * 32 / 256, 256>>>(Wk, bq, w2);
    rb_kernel<<<DM / 32, 256>>>(Wo, bv, bo, rb);
    vvec_kernel<<<MROWS * 32 / 256, 256>>>(x, w2, v);

    // ---- GT = Wk*Wq^T ; HT = Wo^T*Wv^T-form (z=2, FULL 3-term) ----------------
    {
        dim3 grid(DM / TN, DM / TM, 2), blk(256);
        tc_gemm<1, false, false, false, false, 3><<<grid, blk, SMEM_DYN>>>(
            wAh, wAl, wBh, wBl, nullptr, nullptr, gh, gl,
            DM, DM, DM, DM, 1.f,
            (size_t)DM * DM, (size_t)DM * DM, (size_t)DM * DM);
    }

    // ---- QG = x*GT (2-term accurate compute, hi-only output) -------------------
    {
        dim3 grid(DM / TN, MROWS / TM, 1), blk(256);
        tc_gemm<2, false, false, false, false, 2><<<grid, blk, SMEM_DYN>>>(
            xh, xl, gh, gl, nullptr, nullptr, qgh, nullptr,
            DM, DM, DM, DM, 1.f, 0, 0, 0);
    }

    // ---- XHT[d][s] = HT(d,:) . x(s,:)  (1-term, f16 hi out, ldC = MROWS) --------
    {
        dim3 grid(MROWS / TN, DM / TM, 1), blk(256);
        tc_gemm<2, false, false, false, false, 1><<<grid, blk, SMEM_DYN>>>(
            gh + (size_t)DM * DM, nullptr, xh, nullptr,
            nullptr, nullptr, xth, nullptr,
            DM, DM, DM, MROWS, 1.f, 0, 0, 0);
    }

    // ---- scores core = 0.125 * QG @ x^T (triangular grid, 1-term) --------------
    {
        dim3 grid(136, 1, BATCH), blk(256);
        tc_gemm<0, false, true, false, false, 1><<<grid, blk, SMEM_DYN>>>(
            qgh, nullptr, xh, nullptr, nullptr, p, nullptr, nullptr,
            DM, DM, DM, SEQ, 0.125f,
            (size_t)SEQ * DM, (size_t)SEQ * DM, (size_t)SEQ * SEQ);
    }

    // ---- softmax over (scores + 0.125*v[j]) -> f16 hi weights -------------------
    softmax_kernel<<<MROWS, 256>>>(p, v, phh);

    // ---- out = P @ XHT^T + (bv*Wo + bo)  (1-term; B rows = XHT rows, ld=MROWS) --
    {
        dim3 grid(DM / TN, SEQ / TM, BATCH), blk(256);
        tc_gemm<0, true, false, true, true, 1><<<grid, blk, SMEM_DYN>>>(
            phh, nullptr, xth, nullptr, rb, out, nullptr, nullptr,
            SEQ, SEQ, MROWS, DM, 1.f,
            (size_t)SEQ * SEQ, (size_t)SEQ, (size_t)SEQ * DM);
    }
}

// round 16
// speedup vs baseline: 4.1783x; 1.1749x over previous
#include <cuda_runtime.h>
#include <cuda_fp16.h>
#include <math_constants.h>
#include <stdint.h>

#define BATCH 4
#define SEQ   2048
#define DM    1024
#define MROWS (BATCH * SEQ)

#define LO_SCALE  2048.0f
#define INV_LO    (1.0f / 2048.0f)

// ---- GEMM tiling (proven 256-thread / 8-warp config) --------------------------
#define TM 128
#define TN 128
#define BK 64                         // f16 elems per K-chunk (128 bytes/row)
#define TILE_BYTES (128 * 128)        // 16 KB per operand tile

typedef __half h16;

// ---- scratch (static __device__: allocation-free) ------------------------------
#define AL1K __align__(1024)
__device__ AL1K h16   g_xh [MROWS * DM];
__device__ AL1K h16   g_wAh[2 * DM * DM];   // [Wk ; Wo^T] split hi
__device__ AL1K h16   g_wAl[2 * DM * DM];
__device__ AL1K h16   g_wBh[2 * DM * DM];   // [Wq ; Wv] split hi
__device__ AL1K h16   g_wBl[2 * DM * DM];
__device__ AL1K h16   g_gh [2 * DM * DM];   // [GT ; HT] split hi
__device__ AL1K h16   g_gl [2 * DM * DM];
__device__ AL1K h16   g_qgh[(size_t)MROWS * DM];      // QG hi
__device__ AL1K h16   g_xth[MROWS * DM];    // XH^T: [DM rows][MROWS cols]
__device__ AL1K float g_p  [(size_t)BATCH * SEQ * SEQ];
__device__ AL1K h16   g_ph [(size_t)BATCH * SEQ * SEQ];
__device__ AL1K float g_w2 [DM];
__device__ AL1K float g_v  [MROWS];
__device__ AL1K float g_rb [DM];

// ---- PTX helpers -----------------------------------------------------------------
__device__ __forceinline__ uint32_t s2u(const void* p) {
    uint32_t a;
    asm("{ .reg .u64 t; cvta.to.shared.u64 t, %1; cvt.u32.u64 %0, t; }" : "=r"(a) : "l"(p));
    return a;
}
__device__ __forceinline__ void cp16(uint32_t saddr, const void* gaddr) {
    asm volatile("cp.async.cg.shared.global [%0], [%1], 16;" :: "r"(saddr), "l"(gaddr));
}
__device__ __forceinline__ void cp_commit() { asm volatile("cp.async.commit_group;"); }
__device__ __forceinline__ void cp_wait2()  { asm volatile("cp.async.wait_group 2;" ::: "memory"); }

__device__ __forceinline__ void ldm4(uint32_t* r, uint32_t addr) {
    asm volatile("ldmatrix.sync.aligned.m8n8.x4.shared.b16 {%0,%1,%2,%3}, [%4];"
                 : "=r"(r[0]), "=r"(r[1]), "=r"(r[2]), "=r"(r[3]) : "r"(addr));
}
__device__ __forceinline__ void mma_f32(float* c, const uint32_t* a, const uint32_t* b) {
    asm volatile(
        "mma.sync.aligned.m16n8k16.row.col.f32.f16.f16.f32 "
        "{%0,%1,%2,%3}, {%4,%5,%6,%7}, {%8,%9}, {%0,%1,%2,%3};"
        : "+f"(c[0]), "+f"(c[1]), "+f"(c[2]), "+f"(c[3])
        : "r"(a[0]), "r"(a[1]), "r"(a[2]), "r"(a[3]), "r"(b[0]), "r"(b[1]));
}
__device__ __forceinline__ void mma_f16(uint32_t* c, const uint32_t* a, const uint32_t* b) {
    asm volatile(
        "mma.sync.aligned.m16n8k16.row.col.f16.f16.f16.f16 "
        "{%0,%1}, {%2,%3,%4,%5}, {%6,%7}, {%0,%1};"
        : "+r"(c[0]), "+r"(c[1])
        : "r"(a[0]), "r"(a[1]), "r"(a[2]), "r"(a[3]), "r"(b[0]), "r"(b[1]));
}
__device__ __forceinline__ uint32_t pk2(float a, float b) {
    __half2 t = __floats2half2_rn(a, b);
    return *reinterpret_cast<uint32_t*>(&t);
}

// ============================================================================
// Tensor-core GEMM, 256 threads, 8 warps, warp tile 32x64 (proven config).
//   C[M,N] = scale*((Ahi+Alo/2048)[M,K] @ ((Bhi+Blo/2048)[N,K])^T)+bias
//   NTERM=3: AhBh(f32)+AhBl(f16)+AlBh(f16). NTERM=2: AhBh+AlBh. NTERM=1: AhBh.
//   Compact smem stages: only the tiles a given NTERM consumes are resident.
//     NTERM=1: 2 tiles/stage (32KB) -> 96KB total -> 2 CTAs/SM (MINB=2).
//   OUTMODE 0: fp32 out. 1: f16 split out (lo x2048). 2: f16 hi-only out.
//   TRI: blockIdx.x encodes lower-triangle tile; PVLIM: K truncated; REVY: heavy first.
// ============================================================================
template<int OUTMODE, bool HAS_BIAS, bool TRI, bool PVLIM, bool REVY, int NTERM, int MINB>
__global__ __launch_bounds__(256, MINB)
void tc_gemm(const h16* __restrict__ Ah, const h16* __restrict__ Al,
             const h16* __restrict__ Bh, const h16* __restrict__ Bl,
             const float* __restrict__ bias,
             float* __restrict__ Cf, h16* __restrict__ Ch, h16* __restrict__ Cl,
             int Kfull, int ldA, int ldB, int ldC, float scale,
             size_t sA, size_t sB, size_t sC)
{
    // compact tile offsets within a stage
    constexpr uint32_t OFF_AH = 0;
    constexpr uint32_t OFF_AL = TILE_BYTES;                         // NTERM>=2 only
    constexpr uint32_t OFF_BH = (NTERM >= 2 ? 2u : 1u) * TILE_BYTES;
    constexpr uint32_t OFF_BL = 3u * TILE_BYTES;                    // NTERM==3 only
    constexpr uint32_t STAGE  = (NTERM == 3 ? 4u : (NTERM == 2 ? 3u : 2u)) * TILE_BYTES;

    int bm, bn;
    if (TRI) {
        const int t = blockIdx.x;
        int b_ = (int)((sqrtf(8.f * (float)t + 1.f) - 1.f) * 0.5f);
        while ((b_ + 1) * (b_ + 2) / 2 <= t) b_++;
        while (b_ * (b_ + 1) / 2 > t) b_--;
        bm = b_;
        bn = t - b_ * (b_ + 1) / 2;
    } else {
        bm = REVY ? (gridDim.y - 1 - blockIdx.y) : blockIdx.y;
        bn = blockIdx.x;
    }
    const int m0 = bm * TM;
    const int n0 = bn * TN;

    const int z = blockIdx.z;
    Ah += (size_t)z * sA;  if (NTERM >= 2) Al += (size_t)z * sA;
    Bh += (size_t)z * sB;  if (NTERM >= 3) Bl += (size_t)z * sB;

    extern __shared__ char dsm[];
    const uint32_t smem = s2u(dsm);

    const int tid  = threadIdx.x;
    const int wid  = tid >> 5;
    const int lane = tid & 31;
    const int wm   = wid & 3;    // 4 warp-rows  (32 M each)
    const int wn   = wid >> 2;   // 2 warp-cols  (64 N each)

    const int nchunk = PVLIM ? (m0 + TM) / BK : Kfull / BK;

    // ---- loader: each thread = half a row (4x16B segs) of each live tile ------
    const int lrow = tid >> 1;            // 0..127
    const int sb   = (tid & 1) * 4;       // seg base 0 or 4
    const char* gp[4];
    uint32_t    so[4][4];
    {
        const h16* bases[4] = {Ah, Al, Bh, Bl};
        const uint32_t offs[4] = {OFF_AH, OFF_AL, OFF_BH, OFF_BL};
        #pragma unroll
        for (int t = 0; t < 4; t++) {
            if ((t == 1 && NTERM < 2) || (t == 3 && NTERM < 3)) { gp[t] = nullptr; continue; }
            const int off = (t < 2) ? m0 : n0;
            const int ld  = (t < 2) ? ldA : ldB;
            gp[t] = (const char*)(bases[t] + (size_t)(off + lrow) * ld);
            #pragma unroll
            for (int j = 0; j < 4; j++) {
                const int seg = sb + j;
                so[t][j] = (uint32_t)(offs[t] + lrow * 128 +
                                      ((seg ^ (lrow & 7)) << 4));
            }
        }
    }

    auto load_stage = [&](int slot, int chunk) {
        if (chunk < nchunk) {
            const uint32_t s0 = smem + slot * STAGE;
            const size_t goff = (size_t)chunk * 128;
            #pragma unroll
            for (int t = 0; t < 4; t++) {
                if (t == 1 && NTERM < 2) continue;
                if (t == 3 && NTERM < 3) continue;
                #pragma unroll
                for (int j = 0; j < 4; j++)
                    cp16(s0 + so[t][j], gp[t] + goff + (size_t)(sb + j) * 16);
            }
        }
        cp_commit();
    };

    float    accf[2][8][4];
    uint32_t acch[2][8][2];
    #pragma unroll
    for (int a = 0; a < 2; a++)
        #pragma unroll
        for (int b = 0; b < 8; b++) {
            #pragma unroll
            for (int c = 0; c < 4; c++) accf[a][b][c] = 0.f;
            acch[a][b][0] = 0u; acch[a][b][1] = 0u;
        }

    load_stage(0, 0);
    load_stage(1, 1);
    load_stage(2, 2);

    const int a_r  = lane & 15;
    const int a_kh = lane >> 4;
    const int b_nl = ((lane >> 4) & 1) * 8 + (lane & 7);
    const int b_kh = (lane >> 3) & 1;

    for (int i = 0; i < nchunk; i++) {
        cp_wait2();
        __syncthreads();
        const uint32_t s0 = smem + (i % 3) * STAGE;

        #pragma unroll
        for (int kk = 0; kk < 4; kk++) {
            uint32_t ahf[2][4], alf[2][4], bhf[4][4], blf[4][4];
            #pragma unroll
            for (int mt = 0; mt < 2; mt++) {
                const int row = wm * 32 + mt * 16 + a_r;
                const int seg = kk * 2 + a_kh;
                const uint32_t off = (uint32_t)(row * 128 + ((seg ^ (row & 7)) << 4));
                ldm4(ahf[mt], s0 + OFF_AH + off);
                if (NTERM >= 2) ldm4(alf[mt], s0 + OFF_AL + off);
            }
            #pragma unroll
            for (int p = 0; p < 4; p++) {
                const int row = wn * 64 + p * 16 + b_nl;
                const int seg = kk * 2 + b_kh;
                const uint32_t off = (uint32_t)(row * 128 + ((seg ^ (row & 7)) << 4));
                ldm4(bhf[p], s0 + OFF_BH + off);
                if (NTERM >= 3) ldm4(blf[p], s0 + OFF_BL + off);
            }
            #pragma unroll
            for (int mt = 0; mt < 2; mt++)
                #pragma unroll
                for (int nt = 0; nt < 8; nt++)
                    mma_f32(accf[mt][nt], ahf[mt], &bhf[nt >> 1][(nt & 1) * 2]);
            if (NTERM >= 3) {
                #pragma unroll
                for (int mt = 0; mt < 2; mt++)
                    #pragma unroll
                    for (int nt = 0; nt < 8; nt++)
                        mma_f16(acch[mt][nt], ahf[mt], &blf[nt >> 1][(nt & 1) * 2]);
            }
            if (NTERM >= 2) {
                #pragma unroll
                for (int mt = 0; mt < 2; mt++)
                    #pragma unroll
                    for (int nt = 0; nt < 8; nt++)
                        mma_f16(acch[mt][nt], alf[mt], &bhf[nt >> 1][(nt & 1) * 2]);
            }
        }
        __syncthreads();
        load_stage(i % 3, i + 3);
    }

    #pragma unroll
    for (int mt = 0; mt < 2; mt++) {
        #pragma unroll
        for (int h = 0; h < 2; h++) {
            const int row = m0 + wm * 32 + mt * 16 + (lane >> 2) + 8 * h;
            #pragma unroll
            for (int nt = 0; nt < 8; nt++) {
                const int col = n0 + wn * 64 + nt * 8 + (lane & 3) * 2;
                float c0 = 0.f, c1 = 0.f;
                if (NTERM >= 2) {
                    const __half2 hc = *reinterpret_cast<const __half2*>(&acch[mt][nt][h]);
                    c0 = __low2float(hc)  * INV_LO;
                    c1 = __high2float(hc) * INV_LO;
                }
                float v0 = (accf[mt][nt][2 * h + 0] + c0) * scale;
                float v1 = (accf[mt][nt][2 * h + 1] + c1) * scale;
                if (HAS_BIAS) {
                    const float2 bb = *reinterpret_cast<const float2*>(bias + col);
                    v0 += bb.x; v1 += bb.y;
                }
                if (OUTMODE == 0) {
                    *reinterpret_cast<float2*>(
                        Cf + (size_t)z * sC + (size_t)row * ldC + col) =
                        make_float2(v0, v1);
                } else if (OUTMODE == 1) {
                    float h0 = __half2float(__float2half_rn(v0));
                    float h1 = __half2float(__float2half_rn(v1));
                    *reinterpret_cast<uint32_t*>(
                        Ch + (size_t)z * sC + (size_t)row * ldC + col) = pk2(h0, h1);
                    *reinterpret_cast<uint32_t*>(
                        Cl + (size_t)z * sC + (size_t)row * ldC + col) =
                        pk2((v0 - h0) * LO_SCALE, (v1 - h1) * LO_SCALE);
                } else {
                    *reinterpret_cast<uint32_t*>(
                        Ch + (size_t)z * sC + (size_t)row * ldC + col) = pk2(v0, v1);
                }
            }
        }
    }
}

// ============================================================================
// prep kernels
// ============================================================================
__global__ void cvt_h_kernel(const float* __restrict__ in, h16* __restrict__ oh, int n)
{
    int i = blockIdx.x * blockDim.x + threadIdx.x;
    if (i >= n) return;
    oh[i] = __float2half_rn(in[i]);
}

__global__ void split_kernel(const float* __restrict__ in,
                             h16* __restrict__ oh, h16* __restrict__ ol, int n)
{
    int i = blockIdx.x * blockDim.x + threadIdx.x;
    if (i >= n) return;
    float v = in[i];
    h16 h = __float2half_rn(v);
    oh[i] = h;
    ol[i] = __float2half_rn((v - __half2float(h)) * LO_SCALE);
}

__global__ void tsplit_kernel(const float* __restrict__ in,
                              h16* __restrict__ oh, h16* __restrict__ ol,
                              int R, int C)
{
    __shared__ float t[32][33];
    const int c0 = blockIdx.x * 32, r0 = blockIdx.y * 32;
    const int tx = threadIdx.x, ty = threadIdx.y;
    #pragma unroll
    for (int k = 0; k < 4; k++)
        t[ty + 8 * k][tx] = in[(size_t)(r0 + ty + 8 * k) * C + c0 + tx];
    __syncthreads();
    #pragma unroll
    for (int k = 0; k < 4; k++) {
        float v = t[tx][ty + 8 * k];
        h16 h = __float2half_rn(v);
        size_t o = (size_t)(c0 + ty + 8 * k) * R + r0 + tx;
        oh[o] = h;
        ol[o] = __float2half_rn((v - __half2float(h)) * LO_SCALE);
    }
}

__global__ void wkbq_kernel(const float* __restrict__ Wk, const float* __restrict__ bq,
                            float* __restrict__ w2)
{
    int w = (blockIdx.x * blockDim.x + threadIdx.x) >> 5;
    int lane = threadIdx.x & 31;
    if (w >= DM) return;
    float s = 0.f;
    for (int e = lane; e < DM; e += 32) s += Wk[(size_t)w * DM + e] * bq[e];
    #pragma unroll
    for (int o = 16; o > 0; o >>= 1) s += __shfl_down_sync(0xffffffffu, s, o);
    if (lane == 0) w2[w] = s;
}

__global__ void rb_kernel(const float* __restrict__ Wo, const float* __restrict__ bv,
                          const float* __restrict__ bo, float* __restrict__ rb)
{
    __shared__ float red[8][32];
    const int tx = threadIdx.x & 31;
    const int ty = threadIdx.x >> 5;
    const int d = blockIdx.x * 32 + tx;
    float s = 0.f;
    for (int e = ty; e < DM; e += 8)
        s += bv[e] * Wo[(size_t)e * DM + d];
    red[ty][tx] = s;
    __syncthreads();
    if (ty == 0) {
        float t = 0.f;
        #pragma unroll
        for (int j = 0; j < 8; j++) t += red[j][tx];
        rb[d] = t + bo[d];
    }
}

__global__ void vvec_kernel(const float* __restrict__ x, const float* __restrict__ w2,
                            float* __restrict__ v)
{
    int w = (blockIdx.x * blockDim.x + threadIdx.x) >> 5;
    int lane = threadIdx.x & 31;
    if (w >= MROWS) return;
    float s = 0.f;
    for (int d = lane; d < DM; d += 32) s += x[(size_t)w * DM + d] * w2[d];
    #pragma unroll
    for (int o = 16; o > 0; o >>= 1) s += __shfl_down_sync(0xffffffffu, s, o);
    if (lane == 0) v[w] = s;
}

// causal softmax, row cached in smem; writes f16 hi weights only.
__global__ __launch_bounds__(256)
void softmax_kernel(const float* __restrict__ P, const float* __restrict__ V,
                    h16* __restrict__ Ph)
{
    __shared__ float row[SEQ];
    __shared__ float red[256];

    const int rowi = blockIdx.x;
    const int b = rowi / SEQ, q = rowi % SEQ;
    const size_t off = (size_t)b * SEQ * SEQ + (size_t)q * SEQ;
    const float* p = P + off;
    const float* vv = V + (size_t)b * SEQ;
    h16* ph = Ph + off;
    const int n = q + 1;
    const int tid = threadIdx.x;

    float mx = -CUDART_INF_F;
    for (int k = tid; k < n; k += 256) {
        float l = p[k] + 0.125f * vv[k];
        row[k] = l;
        mx = fmaxf(mx, l);
    }
    red[tid] = mx; __syncthreads();
    #pragma unroll
    for (int s = 128; s > 0; s >>= 1) {
        if (tid < s) red[tid] = fmaxf(red[tid], red[tid + s]);
        __syncthreads();
    }
    mx = red[0]; __syncthreads();

    float sum = 0.f;
    for (int k = tid; k < n; k += 256) {
        float e = expf(row[k] - mx);
        row[k] = e;
        sum += e;
    }
    red[tid] = sum; __syncthreads();
    #pragma unroll
    for (int s = 128; s > 0; s >>= 1) {
        if (tid < s) red[tid] += red[tid + s];
        __syncthreads();
    }
    const float inv = 1.f / red[0];
    __syncthreads();

    for (int k = tid; k < n; k += 256) {
        ph[k] = __float2half_rn(row[k] * inv);
    }
    const int fillEnd = ((q >> 7) + 1) << 7;
    for (int k = n + tid; k < fillEnd; k += 256) {
        ph[k] = __float2half_rn(0.f);
    }
}

// ============================================================================
extern "C" void kernel_launch(void* const* d_in, const int*, int, void* d_out, int)
{
    const float* x  = (const float*)d_in[0];
    const float* Wq = (const float*)d_in[1];
    const float* bq = (const float*)d_in[2];
    const float* Wk = (const float*)d_in[3];
    const float* bk = (const float*)d_in[4];   (void)bk;  // cancels in softmax
    const float* Wv = (const float*)d_in[5];
    const float* bv = (const float*)d_in[6];
    const float* Wo = (const float*)d_in[7];
    const float* bo = (const float*)d_in[8];
    float* out = (float*)d_out;

    h16 *xh, *wAh, *wAl, *wBh, *wBl, *gh, *gl, *qgh, *xth, *phh;
    float *p, *w2, *v, *rb;
    cudaGetSymbolAddress((void**)&xh,  g_xh);
    cudaGetSymbolAddress((void**)&wAh, g_wAh); cudaGetSymbolAddress((void**)&wAl, g_wAl);
    cudaGetSymbolAddress((void**)&wBh, g_wBh); cudaGetSymbolAddress((void**)&wBl, g_wBl);
    cudaGetSymbolAddress((void**)&gh,  g_gh);  cudaGetSymbolAddress((void**)&gl,  g_gl);
    cudaGetSymbolAddress((void**)&qgh, g_qgh);
    cudaGetSymbolAddress((void**)&xth, g_xth);
    cudaGetSymbolAddress((void**)&p,   g_p);
    cudaGetSymbolAddress((void**)&phh, g_ph);
    cudaGetSymbolAddress((void**)&w2,  g_w2);  cudaGetSymbolAddress((void**)&v,   g_v);
    cudaGetSymbolAddress((void**)&rb,  g_rb);

    // smem sizes: 3-term = 3*4*16KB = 192KB; 1-term = 3*2*16KB = 96KB
    const int SM3 = 3 * 4 * TILE_BYTES;
    const int SM1 = 3 * 2 * TILE_BYTES;
    cudaFuncSetAttribute(tc_gemm<1, false, false, false, false, 3, 1>, cudaFuncAttributeMaxDynamicSharedMemorySize, SM3);
    cudaFuncSetAttribute(tc_gemm<2, false, false, false, false, 1, 2>, cudaFuncAttributeMaxDynamicSharedMemorySize, SM1);
    cudaFuncSetAttribute(tc_gemm<0, false, true,  false, false, 1, 2>, cudaFuncAttributeMaxDynamicSharedMemorySize, SM1);
    cudaFuncSetAttribute(tc_gemm<0, true,  false, true,  true,  1, 2>, cudaFuncAttributeMaxDynamicSharedMemorySize, SM1);

    // ---- prep: converts/splits + bias vectors --------------------------------
    cvt_h_kernel<<<(MROWS * DM + 255) / 256, 256>>>(x, xh, MROWS * DM);
    split_kernel<<<(DM * DM + 255) / 256, 256>>>(Wk, wAh,           wAl,           DM * DM);
    split_kernel<<<(DM * DM + 255) / 256, 256>>>(Wq, wBh,           wBl,           DM * DM);
    split_kernel<<<(DM * DM + 255) / 256, 256>>>(Wv, wBh + DM * DM, wBl + DM * DM, DM * DM);
    {
        dim3 blk(32, 8), grid(DM / 32, DM / 32);
        tsplit_kernel<<<grid, blk>>>(Wo, wAh + DM * DM, wAl + DM * DM, DM, DM);
    }
    wkbq_kernel<<<DM * 32 / 256, 256>>>(Wk, bq, w2);
    rb_kernel<<<DM / 32, 256>>>(Wo, bv, bo, rb);
    vvec_kernel<<<MROWS * 32 / 256, 256>>>(x, w2, v);

    // ---- GT = Wk*Wq^T ; HT = Wo^T*Wv^T-form (z=2, FULL 3-term) ----------------
    {
        dim3 grid(DM / TN, DM / TM, 2), blk(256);
        tc_gemm<1, false, false, false, false, 3, 1><<<grid, blk, SM3>>>(
            wAh, wAl, wBh, wBl, nullptr, nullptr, gh, gl,
            DM, DM, DM, DM, 1.f,
            (size_t)DM * DM, (size_t)DM * DM, (size_t)DM * DM);
    }

    // ---- QG = x*GT (1-term, hi-only output) -----------------------------------
    {
        dim3 grid(DM / TN, MROWS / TM, 1), blk(256);
        tc_gemm<2, false, false, false, false, 1, 2><<<grid, blk, SM1>>>(
            xh, nullptr, gh, nullptr, nullptr, nullptr, qgh, nullptr,
            DM, DM, DM, DM, 1.f, 0, 0, 0);
    }

    // ---- XHT[d][s] = HT(d,:) . x(s,:)  (1-term, f16 hi out, ldC = MROWS) --------
    {
        dim3 grid(MROWS / TN, DM / TM, 1), blk(256);
        tc_gemm<2, false, false, false, false, 1, 2><<<grid, blk, SM1>>>(
            gh + (size_t)DM * DM, nullptr, xh, nullptr,
            nullptr, nullptr, xth, nullptr,
            DM, DM, DM, MROWS, 1.f, 0, 0, 0);
    }

    // ---- scores core = 0.125 * QG @ x^T (triangular grid, 1-term) --------------
    {
        dim3 grid(136, 1, BATCH), blk(256);
        tc_gemm<0, false, true, false, false, 1, 2><<<grid, blk, SM1>>>(
            qgh, nullptr, xh, nullptr, nullptr, p, nullptr, nullptr,
            DM, DM, DM, SEQ, 0.125f,
            (size_t)SEQ * DM, (size_t)SEQ * DM, (size_t)SEQ * SEQ);
    }

    // ---- softmax over (scores + 0.125*v[j]) -> f16 hi weights -------------------
    softmax_kernel<<<MROWS, 256>>>(p, v, phh);

    // ---- out = P @ XHT^T + (bv*Wo + bo)  (1-term; B rows = XHT rows, ld=MROWS) --
    {
        dim3 grid(DM / TN, SEQ / TM, BATCH), blk(256);
        tc_gemm<0, true, false, true, true, 1, 2><<<grid, blk, SM1>>>(
            phh, nullptr, xth, nullptr, rb, out, nullptr, nullptr,
            SEQ, SEQ, MROWS, DM, 1.f,
            (size_t)SEQ * SEQ, (size_t)SEQ, (size_t)SEQ * DM);
    }
}

// round 17
// speedup vs baseline: 4.5368x; 1.0858x over previous
#include <cuda_runtime.h>
#include <cuda_fp16.h>
#include <math_constants.h>
#include <stdint.h>

#define BATCH 4
#define SEQ   2048
#define DM    1024
#define MROWS (BATCH * SEQ)

#define LO_SCALE  2048.0f
#define INV_LO    (1.0f / 2048.0f)

// ---- GEMM tiling (proven 256-thread / 8-warp config) --------------------------
#define TM 128
#define TN 128
#define BK 64                         // f16 elems per K-chunk (128 bytes/row)
#define TILE_BYTES (128 * 128)        // 16 KB per operand tile
#define QG_TILES 512                  // (DM/TN)*(MROWS/TM) for the fused launch

typedef __half h16;

// ---- scratch (static __device__: allocation-free) ------------------------------
#define AL1K __align__(1024)
__device__ AL1K h16   g_xh [MROWS * DM];
__device__ AL1K h16   g_wAh[2 * DM * DM];   // [Wk ; Wo^T] split hi
__device__ AL1K h16   g_wAl[2 * DM * DM];   // [Wk ; Wo^T] split lo (x2048)
__device__ AL1K h16   g_wBh[2 * DM * DM];   // [Wq ; Wv] hi only
__device__ AL1K h16   g_gh [2 * DM * DM];   // [GT ; HT] hi only
__device__ AL1K h16   g_qgh[(size_t)MROWS * DM];      // QG hi
__device__ AL1K h16   g_xth[MROWS * DM];    // XH^T: [DM rows][MROWS cols]
__device__ AL1K float g_p  [(size_t)BATCH * SEQ * SEQ];
__device__ AL1K h16   g_ph [(size_t)BATCH * SEQ * SEQ];
__device__ AL1K float g_w2 [DM];
__device__ AL1K float g_v  [MROWS];
__device__ AL1K float g_rb [DM];

// ---- PTX helpers -----------------------------------------------------------------
__device__ __forceinline__ uint32_t s2u(const void* p) {
    uint32_t a;
    asm("{ .reg .u64 t; cvta.to.shared.u64 t, %1; cvt.u32.u64 %0, t; }" : "=r"(a) : "l"(p));
    return a;
}
__device__ __forceinline__ void cp16(uint32_t saddr, const void* gaddr) {
    asm volatile("cp.async.cg.shared.global [%0], [%1], 16;" :: "r"(saddr), "l"(gaddr));
}
__device__ __forceinline__ void cp_commit() { asm volatile("cp.async.commit_group;"); }
__device__ __forceinline__ void cp_wait2()  { asm volatile("cp.async.wait_group 2;" ::: "memory"); }

__device__ __forceinline__ void ldm4(uint32_t* r, uint32_t addr) {
    asm volatile("ldmatrix.sync.aligned.m8n8.x4.shared.b16 {%0,%1,%2,%3}, [%4];"
                 : "=r"(r[0]), "=r"(r[1]), "=r"(r[2]), "=r"(r[3]) : "r"(addr));
}
__device__ __forceinline__ void mma_f32(float* c, const uint32_t* a, const uint32_t* b) {
    asm volatile(
        "mma.sync.aligned.m16n8k16.row.col.f32.f16.f16.f32 "
        "{%0,%1,%2,%3}, {%4,%5,%6,%7}, {%8,%9}, {%0,%1,%2,%3};"
        : "+f"(c[0]), "+f"(c[1]), "+f"(c[2]), "+f"(c[3])
        : "r"(a[0]), "r"(a[1]), "r"(a[2]), "r"(a[3]), "r"(b[0]), "r"(b[1]));
}
__device__ __forceinline__ void mma_f16(uint32_t* c, const uint32_t* a, const uint32_t* b) {
    asm volatile(
        "mma.sync.aligned.m16n8k16.row.col.f16.f16.f16.f16 "
        "{%0,%1}, {%2,%3,%4,%5}, {%6,%7}, {%0,%1};"
        : "+r"(c[0]), "+r"(c[1])
        : "r"(a[0]), "r"(a[1]), "r"(a[2]), "r"(a[3]), "r"(b[0]), "r"(b[1]));
}
__device__ __forceinline__ uint32_t pk2(float a, float b) {
    __half2 t = __floats2half2_rn(a, b);
    return *reinterpret_cast<uint32_t*>(&t);
}

// ============================================================================
// Tensor-core GEMM, 256 threads, 8 warps, warp tile 32x64 (proven config).
//   C[M,N] = scale*((Ahi+Alo/2048)[M,K] @ ((Bhi+Blo/2048)[N,K])^T)+bias
//   NTERM=3: AhBh(f32)+AhBl(f16)+AlBh(f16). NTERM=2: AhBh+AlBh. NTERM=1: AhBh.
//   Compact smem stages (only live tiles resident):
//     NTERM=1: 2 tiles/stage -> 96KB total -> 2 CTAs/SM (MINB=2).
//     NTERM=2: 3 tiles/stage -> 144KB total -> 1 CTA/SM.
//   OUTMODE 0: fp32 out. 1: f16 split out (lo x2048). 2: f16 hi-only out.
//   TRI : blockIdx.x encodes lower-triangle tile.
//   FUSE: flat grid; t<QG_TILES -> (Ah,Bh,Ch); else alternate set (Al,Bl,Cl)
//         with ldC2 passed via sC. (NTERM must be 1.)
//   PVLIM: K truncated at causal boundary.  REVY: heavy CTAs first.
// ============================================================================
template<int OUTMODE, bool HAS_BIAS, bool TRI, bool FUSE, bool PVLIM, bool REVY,
         int NTERM, int MINB>
__global__ __launch_bounds__(256, MINB)
void tc_gemm(const h16* __restrict__ Ah, const h16* __restrict__ Al,
             const h16* __restrict__ Bh, const h16* __restrict__ Bl,
             const float* __restrict__ bias,
             float* __restrict__ Cf, h16* __restrict__ Ch, h16* __restrict__ Cl,
             int Kfull, int ldA, int ldB, int ldC, float scale,
             size_t sA, size_t sB, size_t sC)
{
    constexpr uint32_t OFF_AH = 0;
    constexpr uint32_t OFF_AL = TILE_BYTES;                         // NTERM>=2 only
    constexpr uint32_t OFF_BH = (NTERM >= 2 ? 2u : 1u) * TILE_BYTES;
    constexpr uint32_t OFF_BL = 3u * TILE_BYTES;                    // NTERM==3 only
    constexpr uint32_t STAGE  = (NTERM == 3 ? 4u : (NTERM == 2 ? 3u : 2u)) * TILE_BYTES;

    int bm, bn;
    if (TRI) {
        const int t = blockIdx.x;
        int b_ = (int)((sqrtf(8.f * (float)t + 1.f) - 1.f) * 0.5f);
        while ((b_ + 1) * (b_ + 2) / 2 <= t) b_++;
        while (b_ * (b_ + 1) / 2 > t) b_--;
        bm = b_;
        bn = t - b_ * (b_ + 1) / 2;
    } else if (FUSE) {
        const int t = blockIdx.x;
        if (t < QG_TILES) {                 // QG tile: M=MROWS, N=DM
            bm = t >> 3;  bn = t & 7;
        } else {                            // XHT tile: M=DM, N=MROWS
            const int u = t - QG_TILES;
            bm = u >> 6;  bn = u & 63;
            Ah = Al; Bh = Bl; Ch = Cl;
            ldC = (int)sC;
        }
    } else {
        bm = REVY ? (gridDim.y - 1 - blockIdx.y) : blockIdx.y;
        bn = blockIdx.x;
    }
    const int m0 = bm * TM;
    const int n0 = bn * TN;

    const int z = blockIdx.z;
    if (!FUSE) {
        Ah += (size_t)z * sA;  if (NTERM >= 2) Al += (size_t)z * sA;
        Bh += (size_t)z * sB;  if (NTERM >= 3) Bl += (size_t)z * sB;
    }

    extern __shared__ char dsm[];
    const uint32_t smem = s2u(dsm);

    const int tid  = threadIdx.x;
    const int wid  = tid >> 5;
    const int lane = tid & 31;
    const int wm   = wid & 3;    // 4 warp-rows  (32 M each)
    const int wn   = wid >> 2;   // 2 warp-cols  (64 N each)

    const int nchunk = PVLIM ? (m0 + TM) / BK : Kfull / BK;

    // ---- loader: each thread = half a row (4x16B segs) of each live tile ------
    const int lrow = tid >> 1;            // 0..127
    const int sb   = (tid & 1) * 4;       // seg base 0 or 4
    const char* gp[4];
    uint32_t    so[4][4];
    {
        const h16* bases[4] = {Ah, Al, Bh, Bl};
        const uint32_t offs[4] = {OFF_AH, OFF_AL, OFF_BH, OFF_BL};
        #pragma unroll
        for (int t = 0; t < 4; t++) {
            if ((t == 1 && NTERM < 2) || (t == 3 && NTERM < 3)) { gp[t] = nullptr; continue; }
            const int off = (t < 2) ? m0 : n0;
            const int ld  = (t < 2) ? ldA : ldB;
            gp[t] = (const char*)(bases[t] + (size_t)(off + lrow) * ld);
            #pragma unroll
            for (int j = 0; j < 4; j++) {
                const int seg = sb + j;
                so[t][j] = (uint32_t)(offs[t] + lrow * 128 +
                                      ((seg ^ (lrow & 7)) << 4));
            }
        }
    }

    auto load_stage = [&](int slot, int chunk) {
        if (chunk < nchunk) {
            const uint32_t s0 = smem + slot * STAGE;
            const size_t goff = (size_t)chunk * 128;
            #pragma unroll
            for (int t = 0; t < 4; t++) {
                if (t == 1 && NTERM < 2) continue;
                if (t == 3 && NTERM < 3) continue;
                #pragma unroll
                for (int j = 0; j < 4; j++)
                    cp16(s0 + so[t][j], gp[t] + goff + (size_t)(sb + j) * 16);
            }
        }
        cp_commit();
    };

    float    accf[2][8][4];
    uint32_t acch[2][8][2];
    #pragma unroll
    for (int a = 0; a < 2; a++)
        #pragma unroll
        for (int b = 0; b < 8; b++) {
            #pragma unroll
            for (int c = 0; c < 4; c++) accf[a][b][c] = 0.f;
            acch[a][b][0] = 0u; acch[a][b][1] = 0u;
        }

    load_stage(0, 0);
    load_stage(1, 1);
    load_stage(2, 2);

    const int a_r  = lane & 15;
    const int a_kh = lane >> 4;
    const int b_nl = ((lane >> 4) & 1) * 8 + (lane & 7);
    const int b_kh = (lane >> 3) & 1;

    for (int i = 0; i < nchunk; i++) {
        cp_wait2();
        __syncthreads();
        const uint32_t s0 = smem + (i % 3) * STAGE;

        #pragma unroll
        for (int kk = 0; kk < 4; kk++) {
            uint32_t ahf[2][4], alf[2][4], bhf[4][4], blf[4][4];
            #pragma unroll
            for (int mt = 0; mt < 2; mt++) {
                const int row = wm * 32 + mt * 16 + a_r;
                const int seg = kk * 2 + a_kh;
                const uint32_t off = (uint32_t)(row * 128 + ((seg ^ (row & 7)) << 4));
                ldm4(ahf[mt], s0 + OFF_AH + off);
                if (NTERM >= 2) ldm4(alf[mt], s0 + OFF_AL + off);
            }
            #pragma unroll
            for (int p = 0; p < 4; p++) {
                const int row = wn * 64 + p * 16 + b_nl;
                const int seg = kk * 2 + b_kh;
                const uint32_t off = (uint32_t)(row * 128 + ((seg ^ (row & 7)) << 4));
                ldm4(bhf[p], s0 + OFF_BH + off);
                if (NTERM >= 3) ldm4(blf[p], s0 + OFF_BL + off);
            }
            #pragma unroll
            for (int mt = 0; mt < 2; mt++)
                #pragma unroll
                for (int nt = 0; nt < 8; nt++)
                    mma_f32(accf[mt][nt], ahf[mt], &bhf[nt >> 1][(nt & 1) * 2]);
            if (NTERM >= 3) {
                #pragma unroll
                for (int mt = 0; mt < 2; mt++)
                    #pragma unroll
                    for (int nt = 0; nt < 8; nt++)
                        mma_f16(acch[mt][nt], ahf[mt], &blf[nt >> 1][(nt & 1) * 2]);
            }
            if (NTERM >= 2) {
                #pragma unroll
                for (int mt = 0; mt < 2; mt++)
                    #pragma unroll
                    for (int nt = 0; nt < 8; nt++)
                        mma_f16(acch[mt][nt], alf[mt], &bhf[nt >> 1][(nt & 1) * 2]);
            }
        }
        __syncthreads();
        load_stage(i % 3, i + 3);
    }

    #pragma unroll
    for (int mt = 0; mt < 2; mt++) {
        #pragma unroll
        for (int h = 0; h < 2; h++) {
            const int row = m0 + wm * 32 + mt * 16 + (lane >> 2) + 8 * h;
            #pragma unroll
            for (int nt = 0; nt < 8; nt++) {
                const int col = n0 + wn * 64 + nt * 8 + (lane & 3) * 2;
                float c0 = 0.f, c1 = 0.f;
                if (NTERM >= 2) {
                    const __half2 hc = *reinterpret_cast<const __half2*>(&acch[mt][nt][h]);
                    c0 = __low2float(hc)  * INV_LO;
                    c1 = __high2float(hc) * INV_LO;
                }
                float v0 = (accf[mt][nt][2 * h + 0] + c0) * scale;
                float v1 = (accf[mt][nt][2 * h + 1] + c1) * scale;
                if (HAS_BIAS) {
                    const float2 bb = *reinterpret_cast<const float2*>(bias + col);
                    v0 += bb.x; v1 += bb.y;
                }
                if (OUTMODE == 0) {
                    *reinterpret_cast<float2*>(
                        Cf + (size_t)z * sC + (size_t)row * ldC + col) =
                        make_float2(v0, v1);
                } else if (OUTMODE == 1) {
                    float h0 = __half2float(__float2half_rn(v0));
                    float h1 = __half2float(__float2half_rn(v1));
                    *reinterpret_cast<uint32_t*>(
                        Ch + (size_t)z * sC + (size_t)row * ldC + col) = pk2(h0, h1);
                    *reinterpret_cast<uint32_t*>(
                        Cl + (size_t)z * sC + (size_t)row * ldC + col) =
                        pk2((v0 - h0) * LO_SCALE, (v1 - h1) * LO_SCALE);
                } else {
                    const size_t zoff = FUSE ? 0 : (size_t)z * sC;
                    *reinterpret_cast<uint32_t*>(
                        Ch + zoff + (size_t)row * ldC + col) = pk2(v0, v1);
                }
            }
        }
    }
}

// ============================================================================
// prep kernels
// ============================================================================
__global__ void cvt_h_kernel(const float* __restrict__ in, h16* __restrict__ oh, int n)
{
    int i = blockIdx.x * blockDim.x + threadIdx.x;
    if (i >= n) return;
    oh[i] = __float2half_rn(in[i]);
}

__global__ void split_kernel(const float* __restrict__ in,
                             h16* __restrict__ oh, h16* __restrict__ ol, int n)
{
    int i = blockIdx.x * blockDim.x + threadIdx.x;
    if (i >= n) return;
    float v = in[i];
    h16 h = __float2half_rn(v);
    oh[i] = h;
    ol[i] = __float2half_rn((v - __half2float(h)) * LO_SCALE);
}

__global__ void tsplit_kernel(const float* __restrict__ in,
                              h16* __restrict__ oh, h16* __restrict__ ol,
                              int R, int C)
{
    __shared__ float t[32][33];
    const int c0 = blockIdx.x * 32, r0 = blockIdx.y * 32;
    const int tx = threadIdx.x, ty = threadIdx.y;
    #pragma unroll
    for (int k = 0; k < 4; k++)
        t[ty + 8 * k][tx] = in[(size_t)(r0 + ty + 8 * k) * C + c0 + tx];
    __syncthreads();
    #pragma unroll
    for (int k = 0; k < 4; k++) {
        float v = t[tx][ty + 8 * k];
        h16 h = __float2half_rn(v);
        size_t o = (size_t)(c0 + ty + 8 * k) * R + r0 + tx;
        oh[o] = h;
        ol[o] = __float2half_rn((v - __half2float(h)) * LO_SCALE);
    }
}

__global__ void wkbq_kernel(const float* __restrict__ Wk, const float* __restrict__ bq,
                            float* __restrict__ w2)
{
    int w = (blockIdx.x * blockDim.x + threadIdx.x) >> 5;
    int lane = threadIdx.x & 31;
    if (w >= DM) return;
    float s = 0.f;
    for (int e = lane; e < DM; e += 32) s += Wk[(size_t)w * DM + e] * bq[e];
    #pragma unroll
    for (int o = 16; o > 0; o >>= 1) s += __shfl_down_sync(0xffffffffu, s, o);
    if (lane == 0) w2[w] = s;
}

__global__ void rb_kernel(const float* __restrict__ Wo, const float* __restrict__ bv,
                          const float* __restrict__ bo, float* __restrict__ rb)
{
    __shared__ float red[8][32];
    const int tx = threadIdx.x & 31;
    const int ty = threadIdx.x >> 5;
    const int d = blockIdx.x * 32 + tx;
    float s = 0.f;
    for (int e = ty; e < DM; e += 8)
        s += bv[e] * Wo[(size_t)e * DM + d];
    red[ty][tx] = s;
    __syncthreads();
    if (ty == 0) {
        float t = 0.f;
        #pragma unroll
        for (int j = 0; j < 8; j++) t += red[j][tx];
        rb[d] = t + bo[d];
    }
}

__global__ void vvec_kernel(const float* __restrict__ x, const float* __restrict__ w2,
                            float* __restrict__ v)
{
    int w = (blockIdx.x * blockDim.x + threadIdx.x) >> 5;
    int lane = threadIdx.x & 31;
    if (w >= MROWS) return;
    float s = 0.f;
    for (int d = lane; d < DM; d += 32) s += x[(size_t)w * DM + d] * w2[d];
    #pragma unroll
    for (int o = 16; o > 0; o >>= 1) s += __shfl_down_sync(0xffffffffu, s, o);
    if (lane == 0) v[w] = s;
}

// causal softmax, row cached in smem; writes f16 hi weights only.
__global__ __launch_bounds__(256)
void softmax_kernel(const float* __restrict__ P, const float* __restrict__ V,
                    h16* __restrict__ Ph)
{
    __shared__ float row[SEQ];
    __shared__ float red[256];

    const int rowi = blockIdx.x;
    const int b = rowi / SEQ, q = rowi % SEQ;
    const size_t off = (size_t)b * SEQ * SEQ + (size_t)q * SEQ;
    const float* p = P + off;
    const float* vv = V + (size_t)b * SEQ;
    h16* ph = Ph + off;
    const int n = q + 1;
    const int tid = threadIdx.x;

    float mx = -CUDART_INF_F;
    for (int k = tid; k < n; k += 256) {
        float l = p[k] + 0.125f * vv[k];
        row[k] = l;
        mx = fmaxf(mx, l);
    }
    red[tid] = mx; __syncthreads();
    #pragma unroll
    for (int s = 128; s > 0; s >>= 1) {
        if (tid < s) red[tid] = fmaxf(red[tid], red[tid + s]);
        __syncthreads();
    }
    mx = red[0]; __syncthreads();

    float sum = 0.f;
    for (int k = tid; k < n; k += 256) {
        float e = expf(row[k] - mx);
        row[k] = e;
        sum += e;
    }
    red[tid] = sum; __syncthreads();
    #pragma unroll
    for (int s = 128; s > 0; s >>= 1) {
        if (tid < s) red[tid] += red[tid + s];
        __syncthreads();
    }
    const float inv = 1.f / red[0];
    __syncthreads();

    for (int k = tid; k < n; k += 256) {
        ph[k] = __float2half_rn(row[k] * inv);
    }
    const int fillEnd = ((q >> 7) + 1) << 7;
    for (int k = n + tid; k < fillEnd; k += 256) {
        ph[k] = __float2half_rn(0.f);
    }
}

// ============================================================================
extern "C" void kernel_launch(void* const* d_in, const int*, int, void* d_out, int)
{
    const float* x  = (const float*)d_in[0];
    const float* Wq = (const float*)d_in[1];
    const float* bq = (const float*)d_in[2];
    const float* Wk = (const float*)d_in[3];
    const float* bk = (const float*)d_in[4];   (void)bk;  // cancels in softmax
    const float* Wv = (const float*)d_in[5];
    const float* bv = (const float*)d_in[6];
    const float* Wo = (const float*)d_in[7];
    const float* bo = (const float*)d_in[8];
    float* out = (float*)d_out;

    h16 *xh, *wAh, *wAl, *wBh, *gh, *qgh, *xth, *phh;
    float *p, *w2, *v, *rb;
    cudaGetSymbolAddress((void**)&xh,  g_xh);
    cudaGetSymbolAddress((void**)&wAh, g_wAh); cudaGetSymbolAddress((void**)&wAl, g_wAl);
    cudaGetSymbolAddress((void**)&wBh, g_wBh);
    cudaGetSymbolAddress((void**)&gh,  g_gh);
    cudaGetSymbolAddress((void**)&qgh, g_qgh);
    cudaGetSymbolAddress((void**)&xth, g_xth);
    cudaGetSymbolAddress((void**)&p,   g_p);
    cudaGetSymbolAddress((void**)&phh, g_ph);
    cudaGetSymbolAddress((void**)&w2,  g_w2);  cudaGetSymbolAddress((void**)&v,   g_v);
    cudaGetSymbolAddress((void**)&rb,  g_rb);

    // smem sizes: 2-term = 3*3*16KB = 144KB; 1-term = 3*2*16KB = 96KB
    const int SM2 = 3 * 3 * TILE_BYTES;
    const int SM1 = 3 * 2 * TILE_BYTES;
    cudaFuncSetAttribute(tc_gemm<2, false, false, false, false, false, 2, 1>, cudaFuncAttributeMaxDynamicSharedMemorySize, SM2);
    cudaFuncSetAttribute(tc_gemm<2, false, false, true,  false, false, 1, 2>, cudaFuncAttributeMaxDynamicSharedMemorySize, SM1);
    cudaFuncSetAttribute(tc_gemm<0, false, true,  false, false, false, 1, 2>, cudaFuncAttributeMaxDynamicSharedMemorySize, SM1);
    cudaFuncSetAttribute(tc_gemm<0, true,  false, false, true,  true,  1, 2>, cudaFuncAttributeMaxDynamicSharedMemorySize, SM1);

    // ---- prep: converts/splits + bias vectors --------------------------------
    cvt_h_kernel<<<(MROWS * DM + 255) / 256, 256>>>(x, xh, MROWS * DM);
    split_kernel<<<(DM * DM + 255) / 256, 256>>>(Wk, wAh, wAl, DM * DM);
    cvt_h_kernel<<<(DM * DM + 255) / 256, 256>>>(Wq, wBh,           DM * DM);
    cvt_h_kernel<<<(DM * DM + 255) / 256, 256>>>(Wv, wBh + DM * DM, DM * DM);
    {
        dim3 blk(32, 8), grid(DM / 32, DM / 32);
        tsplit_kernel<<<grid, blk>>>(Wo, wAh + DM * DM, wAl + DM * DM, DM, DM);
    }
    wkbq_kernel<<<DM * 32 / 256, 256>>>(Wk, bq, w2);
    rb_kernel<<<DM / 32, 256>>>(Wo, bv, bo, rb);
    vvec_kernel<<<MROWS * 32 / 256, 256>>>(x, w2, v);

    // ---- GT = Wk*Wq^T ; HT = Wo^T*Wv^T-form (z=2, 2-term, hi-only out) --------
    {
        dim3 grid(DM / TN, DM / TM, 2), blk(256);
        tc_gemm<2, false, false, false, false, false, 2, 1><<<grid, blk, SM2>>>(
            wAh, wAl, wBh, nullptr, nullptr, nullptr, gh, nullptr,
            DM, DM, DM, DM, 1.f,
            (size_t)DM * DM, (size_t)DM * DM, (size_t)DM * DM);
    }

    // ---- fused QG (t<512) + XHT (t>=512) single launch, 1-term ----------------
    //   QG : C[qgh] = xh @ GT^T            (M=MROWS, N=DM,   ldC=DM)
    //   XHT: C[xth] = HT @ xh^T            (M=DM,   N=MROWS, ldC=MROWS via sC)
    {
        dim3 grid(2 * QG_TILES, 1, 1), blk(256);
        tc_gemm<2, false, false, true, false, false, 1, 2><<<grid, blk, SM1>>>(
            xh, gh + (size_t)DM * DM,   // A (QG) / A-alt (XHT)
            gh, xh,                     // B (QG) / B-alt (XHT)
            nullptr, nullptr,
            qgh, xth,                   // C (QG) / C-alt (XHT)
            DM, DM, DM, DM, 1.f,
            0, 0, (size_t)MROWS /* ldC2 */);
    }

    // ---- scores core = 0.125 * QG @ x^T (triangular grid, 1-term) --------------
    {
        dim3 grid(136, 1, BATCH), blk(256);
        tc_gemm<0, false, true, false, false, false, 1, 2><<<grid, blk, SM1>>>(
            qgh, nullptr, xh, nullptr, nullptr, p, nullptr, nullptr,
            DM, DM, DM, SEQ, 0.125f,
            (size_t)SEQ * DM, (size_t)SEQ * DM, (size_t)SEQ * SEQ);
    }

    // ---- softmax over (scores + 0.125*v[j]) -> f16 hi weights -------------------
    softmax_kernel<<<MROWS, 256>>>(p, v, phh);

    // ---- out = P @ XHT^T + (bv*Wo + bo)  (1-term; B rows = XHT rows, ld=MROWS) --
    {
        dim3 grid(DM / TN, SEQ / TM, BATCH), blk(256);
        tc_gemm<0, true, false, false, true, true, 1, 2><<<grid, blk, SM1>>>(
            phh, nullptr, xth, nullptr, rb, out, nullptr, nullptr,
            SEQ, SEQ, MROWS, DM, 1.f,
            (size_t)SEQ * SEQ, (size_t)SEQ, (size_t)SEQ * DM);
    }
}